// round 8
// baseline (speedup 1.0000x reference)
#include <cuda_runtime.h>
#include <cstdint>

#define MQ     50000
#define NSUP   100000
#define HN     32
#define KPN    15
#define CIN    64
#define COUT   64
#define GK     (KPN * CIN)        // 960
#define MB     16
#define NTHR   256
#define INFPT  1.0e6f

#define NSTEP  (GK / 8)           // 120
#define WT_KS  36                 // wT k-row stride (4*g4+q banks distinct)
#define WT_MS  (16 * WT_KS)       // 576 per query
#define FB_PAD 72                 // fbuf row stride (8*q+g4 banks distinct)
#define WGT_MS 1028               // wgt m-row stride, 1028 % 32 == 4

// smem words: wT 16*576 + fbuf 32*72 + wgt 16*1028 + kp 48 + inv 16 + idx 512
#define SMEM_WORDS (MB*WT_MS + HN*FB_PAD + MB*WGT_MS + 48 + MB + MB*HN)
#define SMEM_BYTES (SMEM_WORDS * 4)

__device__ int g_idx_is64;
__device__ unsigned char g_flags[NSUP];
// fragment-packed W (tf32): g_Bf[step][wn(8)][lane] = {B[k0+q][d], B[k0+4+q][d]}, d=wn*8+g4
__device__ float2 g_Bf[NSTEP * 8 * 32];

__device__ __forceinline__ float to_tf32(float x) {
    uint32_t r; asm("cvt.rna.tf32.f32 %0, %1;" : "=r"(r) : "f"(x));
    return __uint_as_float(r);
}
__device__ __forceinline__ void mma_tf32(float4& c, uint32_t a0, uint32_t a1,
                                         uint32_t a2, uint32_t a3,
                                         uint32_t b0, uint32_t b1) {
    asm volatile(
        "mma.sync.aligned.m16n8k8.row.col.f32.tf32.tf32.f32 "
        "{%0,%1,%2,%3}, {%4,%5,%6,%7}, {%8,%9}, {%0,%1,%2,%3};"
        : "+f"(c.x), "+f"(c.y), "+f"(c.z), "+f"(c.w)
        : "r"(a0), "r"(a1), "r"(a2), "r"(a3), "r"(b0), "r"(b1));
}

// ================= prep: flags + B fragment pack + dtype detect ==============
#define FLAG_BLKS ((NSUP + 7) / 8)
#define BF_BLKS   (NSTEP * 8 * 32 / 256)     // 120
__global__ void __launch_bounds__(256) prep_kernel(const float* __restrict__ sfeats,
                                                   const float* __restrict__ wts,
                                                   const unsigned* __restrict__ nbr) {
    const int b = blockIdx.x;
    const int tid = threadIdx.x;

    if (b < FLAG_BLKS) {
        const int n = b * 8 + (tid >> 5);
        if (n >= NSUP) return;
        const int lane = tid & 31;
        const float* row = sfeats + (long long)n * CIN;
        float s = row[lane] + row[lane + 32];
        #pragma unroll
        for (int o = 16; o; o >>= 1) s += __shfl_xor_sync(0xffffffffu, s, o);
        if (lane == 0) g_flags[n] = (s > 0.0f) ? 1 : 0;
        return;
    }
    if (b < FLAG_BLKS + BF_BLKS) {
        const int e = (b - FLAG_BLKS) * 256 + tid;
        const int lane = e & 31;
        const int wn   = (e >> 5) & 7;
        const int step = e >> 8;
        const int q  = lane & 3;
        const int g4 = lane >> 2;
        const int d  = wn * 8 + g4;
        const int kg0 = step * 8 + q;
        g_Bf[e] = make_float2(to_tf32(wts[kg0 * COUT + d]),
                              to_tf32(wts[(kg0 + 4) * COUT + d]));
        return;
    }
    if (tid == 0) {
        int is64 = 1;
        #pragma unroll
        for (int i = 0; i < 64; i++) {
            if (nbr[2 * i + 1] != 0u) { is64 = 0; break; }
        }
        g_idx_is64 = is64;
    }
}

// ================= fused main kernel =================
extern "C" __global__ void __launch_bounds__(NTHR, 2)
kpconv_kernel(const float* __restrict__ qpts,
              const float* __restrict__ spts,
              const float* __restrict__ sfeats,
              const void*  __restrict__ nbr,
              const float* __restrict__ kpts,
              float* __restrict__ out)
{
    extern __shared__ float sm[];
    float* wT_s  = sm;                          // [MB][16][WT_KS], tf32 w transposed
    float* fbuf  = wT_s + MB * WT_MS;           // [HN][FB_PAD], tf32 gathered feats
    float* wgt_s = fbuf + HN * FB_PAD;          // [MB][WGT_MS]
    float* kp_s  = wgt_s + MB * WGT_MS;         // 48
    float* inv_s = kp_s + 48;                   // MB
    int*   idx_s = (int*)(inv_s + MB);          // [MB][HN]

    const int tid = threadIdx.x;
    const int m0  = blockIdx.x * MB;
    const bool is64 = (g_idx_is64 != 0);

    const int wid  = tid >> 5;
    const int lane = tid & 31;
    const int q    = lane & 3;
    const int g4   = lane >> 2;

    if (tid < KPN * 3) kp_s[tid] = kpts[tid];
    __syncthreads();

    // ---------------- Stage A: w[m,h,k] -> wT_s (tf32, transposed) ----------
    #pragma unroll
    for (int it = 0; it < 2; it++) {
        const int p = tid + it * NTHR;          // p < MB*HN = 512
        const int m = p >> 5;
        const int h = p & 31;
        const long long gi = (long long)(m0 + m) * HN + h;
        int idx;
        if (is64) idx = (int)((const long long*)nbr)[gi];
        else      idx = ((const int*)nbr)[gi];
        const bool valid = (idx < NSUP);

        float px, py, pz;
        if (valid) {
            const float* s3 = spts + (long long)idx * 3;
            px = s3[0]; py = s3[1]; pz = s3[2];
        } else {
            px = INFPT; py = INFPT; pz = INFPT;
        }
        const float* q3 = qpts + (long long)(m0 + m) * 3;
        const float rx = px - q3[0];
        const float ry = py - q3[1];
        const float rz = pz - q3[2];

        float* wcol = wT_s + m * WT_MS;
        float wmax = 0.0f;
        #pragma unroll
        for (int k = 0; k < KPN; k++) {
            const float dx = rx - kp_s[k * 3 + 0];
            const float dy = ry - kp_s[k * 3 + 1];
            const float dz = rz - kp_s[k * 3 + 2];
            const float sq = dx * dx + dy * dy + dz * dz;
            const float w  = fmaxf(1.0f - sqrtf(sq) * 0.5f, 0.0f);
            wcol[k * WT_KS + h] = to_tf32(w);
            wmax = fmaxf(wmax, w);
        }
        wcol[15 * WT_KS + h] = 0.0f;            // pad k-row

        bool real = false;
        if (valid) real = (g_flags[idx] != 0);
        const unsigned bal = __ballot_sync(0xffffffffu, real);
        if ((tid & 31) == 0) inv_s[m] = 1.0f / (float)max(__popc(bal), 1);

        idx_s[p] = (wmax > 0.0f) ? idx : -1;
    }
    __syncthreads();

    // ---------------- Stage B (mma): wgt[m] = wT(16x32) @ f(32x64) ----------
    {
        const int c0 = wid * 8;                 // warp's c-tile
        #pragma unroll 1
        for (int g = 0; g < MB; g++) {
            // gather f rows for query g into fbuf (tf32-rounded, zeros if skipped)
            #pragma unroll
            for (int it = 0; it < 2; it++) {
                const int i = tid + it * NTHR;  // 0..511
                const int h = i >> 4;
                const int cc = (i & 15) * 4;
                const int idx = idx_s[g * HN + h];
                float4 v = make_float4(0.f, 0.f, 0.f, 0.f);
                if (idx >= 0) {
                    const float4 f = *(const float4*)(sfeats + (long long)idx * CIN + cc);
                    v = make_float4(to_tf32(f.x), to_tf32(f.y),
                                    to_tf32(f.z), to_tf32(f.w));
                }
                *(float4*)(fbuf + h * FB_PAD + cc) = v;
            }
            __syncthreads();

            float4 acc = make_float4(0.f, 0.f, 0.f, 0.f);
            const float* wtm = wT_s + g * WT_MS;
            #pragma unroll
            for (int s = 0; s < 4; s++) {
                const int h0 = s * 8;
                const uint32_t a0 = __float_as_uint(wtm[g4 * WT_KS + h0 + q]);
                const uint32_t a1 = __float_as_uint(wtm[(g4 + 8) * WT_KS + h0 + q]);
                const uint32_t a2 = __float_as_uint(wtm[g4 * WT_KS + h0 + q + 4]);
                const uint32_t a3 = __float_as_uint(wtm[(g4 + 8) * WT_KS + h0 + q + 4]);
                const uint32_t b0 = __float_as_uint(fbuf[(h0 + q) * FB_PAD + c0 + g4]);
                const uint32_t b1 = __float_as_uint(fbuf[(h0 + q + 4) * FB_PAD + c0 + g4]);
                mma_tf32(acc, a0, a1, a2, a3, b0, b1);
            }

            // C[k=g4][c0+2q..+1], C[k=g4+8][...] -> wgt_s (tf32)
            float* wg = wgt_s + g * WGT_MS;
            *(float2*)(wg + g4 * CIN + c0 + 2 * q) =
                make_float2(to_tf32(acc.x), to_tf32(acc.y));
            if (g4 + 8 < KPN)
                *(float2*)(wg + (g4 + 8) * CIN + c0 + 2 * q) =
                    make_float2(to_tf32(acc.z), to_tf32(acc.w));
            else
                *(float2*)(wg + 15 * CIN + c0 + 2 * q) = make_float2(0.f, 0.f);
            __syncthreads();
        }
    }

    // ---------------- Stage C (mma): out = wgt(16x960) @ W(960x64) ----------
    {
        float4 ca = make_float4(0.f, 0.f, 0.f, 0.f);
        float4 cb = make_float4(0.f, 0.f, 0.f, 0.f);

        const float* ar0 = wgt_s + g4 * WGT_MS;
        const float* ar1 = wgt_s + (g4 + 8) * WGT_MS;
        const float2* bp = g_Bf + wid * 32 + lane;

        #pragma unroll 4
        for (int s = 0; s < NSTEP; s += 2) {
            {
                const int k0 = s * 8;
                const uint32_t a0 = __float_as_uint(ar0[k0 + q]);
                const uint32_t a1 = __float_as_uint(ar1[k0 + q]);
                const uint32_t a2 = __float_as_uint(ar0[k0 + q + 4]);
                const uint32_t a3 = __float_as_uint(ar1[k0 + q + 4]);
                const float2 b = bp[(size_t)s * 256];
                mma_tf32(ca, a0, a1, a2, a3,
                         __float_as_uint(b.x), __float_as_uint(b.y));
            }
            {
                const int k0 = (s + 1) * 8;
                const uint32_t a0 = __float_as_uint(ar0[k0 + q]);
                const uint32_t a1 = __float_as_uint(ar1[k0 + q]);
                const uint32_t a2 = __float_as_uint(ar0[k0 + q + 4]);
                const uint32_t a3 = __float_as_uint(ar1[k0 + q + 4]);
                const float2 b = bp[(size_t)(s + 1) * 256];
                mma_tf32(cb, a0, a1, a2, a3,
                         __float_as_uint(b.x), __float_as_uint(b.y));
            }
        }
        ca.x += cb.x; ca.y += cb.y; ca.z += cb.z; ca.w += cb.w;

        const float inv0 = inv_s[g4];
        const float inv1 = inv_s[g4 + 8];
        const int col = wid * 8 + 2 * q;
        *(float2*)(out + (size_t)(m0 + g4) * COUT + col) =
            make_float2(ca.x * inv0, ca.y * inv0);
        *(float2*)(out + (size_t)(m0 + g4 + 8) * COUT + col) =
            make_float2(ca.z * inv1, ca.w * inv1);
    }
}

// ================= launch =================
extern "C" void kernel_launch(void* const* d_in, const int* in_sizes, int n_in,
                              void* d_out, int out_size) {
    const float* qpts = nullptr;
    const float* spts = nullptr;
    const float* sfeats = nullptr;
    const void*  nbr = nullptr;
    const float* wts = nullptr;
    const float* kpts = nullptr;
    for (int i = 0; i < n_in; i++) {
        switch (in_sizes[i]) {
            case MQ * 3:        qpts   = (const float*)d_in[i]; break;
            case NSUP * 3:      spts   = (const float*)d_in[i]; break;
            case NSUP * CIN:    sfeats = (const float*)d_in[i]; break;
            case MQ * HN:       nbr    = d_in[i];               break;
            case KPN*CIN*COUT:  wts    = (const float*)d_in[i]; break;
            case KPN * 3:       kpts   = (const float*)d_in[i]; break;
            default: break;
        }
    }
    float* outp = (float*)d_out;

    cudaFuncSetAttribute(kpconv_kernel,
                         cudaFuncAttributeMaxDynamicSharedMemorySize, SMEM_BYTES);

    prep_kernel<<<FLAG_BLKS + BF_BLKS + 1, 256>>>(sfeats, wts, (const unsigned*)nbr);
    kpconv_kernel<<<MQ / MB, NTHR, SMEM_BYTES>>>(
        qpts, spts, sfeats, nbr, kpts, outp);
}

// round 9
// speedup vs baseline: 1.4236x; 1.4236x over previous
#include <cuda_runtime.h>
#include <cstdint>

#define MQ     50000
#define NSUP   100000
#define HN     32
#define KPN    15
#define CIN    64
#define COUT   64
#define MB     16
#define NTHR   256
#define INFPT  1.0e6f

#define NSTEPC 128                // stage-C steps over 1024 permuted contraction dim
#define WT_KS  36                 // wT k-row stride (banks 4*g4+q distinct)
#define WT_MS  (16 * WT_KS)       // 576 per query
#define WGT_MS 1028               // wgt m-row stride (1024 + pad, 1028%32==4)

// smem words: wT 16*576 + wgt 16*1028 + kp 48 + inv 16 + idx 512
#define SMEM_WORDS (MB*WT_MS + MB*WGT_MS + 48 + MB + MB*HN)
#define SMEM_BYTES (SMEM_WORDS * 4)

__device__ int g_idx_is64;
__device__ unsigned char g_flags[NSUP];
__device__ float g_sfr[(size_t)NSUP * CIN];   // tf32-rounded sfeats
// fragment-packed W for stage C over the PERMUTED 1024-dim contraction order
__device__ float2 g_Bf[NSTEPC * 8 * 32];

__device__ __forceinline__ float to_tf32(float x) {
    uint32_t r; asm("cvt.rna.tf32.f32 %0, %1;" : "=r"(r) : "f"(x));
    return __uint_as_float(r);
}
__device__ __forceinline__ void mma_tf32(float4& c, uint32_t a0, uint32_t a1,
                                         uint32_t a2, uint32_t a3,
                                         uint32_t b0, uint32_t b1) {
    asm volatile(
        "mma.sync.aligned.m16n8k8.row.col.f32.tf32.tf32.f32 "
        "{%0,%1,%2,%3}, {%4,%5,%6,%7}, {%8,%9}, {%0,%1,%2,%3};"
        : "+f"(c.x), "+f"(c.y), "+f"(c.z), "+f"(c.w)
        : "r"(a0), "r"(a1), "r"(a2), "r"(a3), "r"(b0), "r"(b1));
}

// permuted contraction index j -> W value (k<15 ? wts[k][c][d] : 0)
__device__ __forceinline__ float bf_val(const float* wts, int j, int d) {
    const int l    = (j >> 2) & 31;
    const int nt   = j >> 7;
    const int comp = j & 3;
    const int qq = l & 3;
    const int gg = l >> 2;
    const int k  = gg + ((comp >> 1) << 3);
    const int c  = (nt << 3) + (qq << 1) + (comp & 1);
    return (k < KPN) ? to_tf32(wts[(k * CIN + c) * COUT + d]) : 0.0f;
}

// ================= prep: flags + sfeats round + B pack + dtype detect ========
#define FLAG_BLKS ((NSUP + 7) / 8)
#define BF_BLKS   (NSTEPC * 8 * 32 / 256)    // 128
__global__ void __launch_bounds__(256) prep_kernel(const float* __restrict__ sfeats,
                                                   const float* __restrict__ wts,
                                                   const unsigned* __restrict__ nbr) {
    const int b = blockIdx.x;
    const int tid = threadIdx.x;

    if (b < FLAG_BLKS) {
        const int n = b * 8 + (tid >> 5);
        if (n >= NSUP) return;
        const int lane = tid & 31;
        const float* row = sfeats + (long long)n * CIN;
        const float v0 = row[lane];
        const float v1 = row[lane + 32];
        g_sfr[(size_t)n * CIN + lane]      = to_tf32(v0);
        g_sfr[(size_t)n * CIN + lane + 32] = to_tf32(v1);
        float s = v0 + v1;
        #pragma unroll
        for (int o = 16; o; o >>= 1) s += __shfl_xor_sync(0xffffffffu, s, o);
        if (lane == 0) g_flags[n] = (s > 0.0f) ? 1 : 0;
        return;
    }
    if (b < FLAG_BLKS + BF_BLKS) {
        const int e = (b - FLAG_BLKS) * 256 + tid;
        const int lane = e & 31;
        const int wn   = (e >> 5) & 7;
        const int step = e >> 8;              // 0..127
        const int q  = lane & 3;
        const int g4 = lane >> 2;
        const int d  = wn * 8 + g4;
        const int j0 = step * 8 + q;
        g_Bf[e] = make_float2(bf_val(wts, j0, d), bf_val(wts, j0 + 4, d));
        return;
    }
    if (tid == 0) {
        int is64 = 1;
        #pragma unroll
        for (int i = 0; i < 64; i++) {
            if (nbr[2 * i + 1] != 0u) { is64 = 0; break; }
        }
        g_idx_is64 = is64;
    }
}

// ================= fused main kernel =================
extern "C" __global__ void __launch_bounds__(NTHR, 2)
kpconv_kernel(const float* __restrict__ qpts,
              const float* __restrict__ spts,
              const void*  __restrict__ nbr,
              const float* __restrict__ kpts,
              float* __restrict__ out)
{
    extern __shared__ float sm[];
    float* wT_s  = sm;                          // [MB][16][WT_KS] tf32 w transposed
    float* wgt_s = sm + MB * WT_MS;             // [MB][WGT_MS] fragment-order wgt
    float* kp_s  = wgt_s + MB * WGT_MS;         // 48
    float* inv_s = kp_s + 48;                   // MB
    int*   idx_s = (int*)(inv_s + MB);          // [MB][HN]

    const int tid = threadIdx.x;
    const int m0  = blockIdx.x * MB;
    const bool is64 = (g_idx_is64 != 0);

    const int wid  = tid >> 5;
    const int lane = tid & 31;
    const int q    = lane & 3;
    const int g4   = lane >> 2;

    if (tid < KPN * 3) kp_s[tid] = kpts[tid];
    __syncthreads();

    // ---------------- Stage A: w[m,h,k] -> wT_s (tf32, transposed) ----------
    #pragma unroll
    for (int it = 0; it < 2; it++) {
        const int p = tid + it * NTHR;          // p < MB*HN = 512
        const int m = p >> 5;
        const int h = p & 31;
        const long long gi = (long long)(m0 + m) * HN + h;
        int idx;
        if (is64) idx = (int)((const long long*)nbr)[gi];
        else      idx = ((const int*)nbr)[gi];
        const bool valid = (idx < NSUP);

        float px, py, pz;
        if (valid) {
            const float* s3 = spts + (long long)idx * 3;
            px = s3[0]; py = s3[1]; pz = s3[2];
        } else {
            px = INFPT; py = INFPT; pz = INFPT;
        }
        const float* q3 = qpts + (long long)(m0 + m) * 3;
        const float rx = px - q3[0];
        const float ry = py - q3[1];
        const float rz = pz - q3[2];

        float* wcol = wT_s + m * WT_MS;
        float wmax = 0.0f;
        #pragma unroll
        for (int k = 0; k < KPN; k++) {
            const float dx = rx - kp_s[k * 3 + 0];
            const float dy = ry - kp_s[k * 3 + 1];
            const float dz = rz - kp_s[k * 3 + 2];
            const float sq = dx * dx + dy * dy + dz * dz;
            const float w  = fmaxf(1.0f - sqrtf(sq) * 0.5f, 0.0f);
            wcol[k * WT_KS + h] = to_tf32(w);
            wmax = fmaxf(wmax, w);
        }
        wcol[15 * WT_KS + h] = 0.0f;            // zero pad k-row

        bool real = false;
        if (valid) real = (g_flags[idx] != 0);
        const unsigned bal = __ballot_sync(0xffffffffu, real);
        if ((tid & 31) == 0) inv_s[m] = 1.0f / (float)max(__popc(bal), 1);

        idx_s[p] = (wmax > 0.0f) ? idx : -1;
    }
    __syncthreads();

    // ---------------- Stage B (mma, warp-private, no barriers) --------------
    // warp wid handles queries 2*wid and 2*wid+1: wgt[m] = wT(16x32) @ f(32x64)
    {
        #pragma unroll
        for (int half = 0; half < 2; half++) {
            const int mq = 2 * wid + half;
            const int*   irow = idx_s + mq * HN;
            const float* wtm  = wT_s + mq * WT_MS;

            float4 acc[8];
            #pragma unroll
            for (int nt = 0; nt < 8; nt++) acc[nt] = make_float4(0.f, 0.f, 0.f, 0.f);

            #pragma unroll
            for (int s = 0; s < 4; s++) {
                const int h0 = s * 8;
                const uint32_t a0 = __float_as_uint(wtm[g4 * WT_KS + h0 + q]);
                const uint32_t a1 = __float_as_uint(wtm[(g4 + 8) * WT_KS + h0 + q]);
                const uint32_t a2 = __float_as_uint(wtm[g4 * WT_KS + h0 + q + 4]);
                const uint32_t a3 = __float_as_uint(wtm[(g4 + 8) * WT_KS + h0 + q + 4]);
                const int i0 = irow[h0 + q];
                const int i1 = irow[h0 + q + 4];
                const bool v0 = (i0 >= 0);
                const bool v1 = (i1 >= 0);
                const float* p0 = g_sfr + (size_t)(v0 ? i0 : 0) * CIN + g4;
                const float* p1 = g_sfr + (size_t)(v1 ? i1 : 0) * CIN + g4;
                #pragma unroll
                for (int nt = 0; nt < 8; nt++) {
                    const float b0 = v0 ? p0[nt * 8] : 0.0f;
                    const float b1 = v1 ? p1[nt * 8] : 0.0f;
                    mma_tf32(acc[nt], a0, a1, a2, a3,
                             __float_as_uint(b0), __float_as_uint(b1));
                }
            }

            // fragment-native epilogue: word j = nt*128 + lane*4 + comp
            float* wq = wgt_s + mq * WGT_MS;
            #pragma unroll
            for (int nt = 0; nt < 8; nt++) {
                *(float4*)(wq + nt * 128 + lane * 4) =
                    make_float4(to_tf32(acc[nt].x), to_tf32(acc[nt].y),
                                to_tf32(acc[nt].z), to_tf32(acc[nt].w));
            }
        }
    }
    __syncthreads();

    // ---------------- Stage C (mma): out = wgt(16x1024) @ Bf, scaled --------
    {
        float4 ca = make_float4(0.f, 0.f, 0.f, 0.f);
        float4 cb = make_float4(0.f, 0.f, 0.f, 0.f);

        const float* ar0 = wgt_s + g4 * WGT_MS;
        const float* ar1 = wgt_s + (g4 + 8) * WGT_MS;
        const float2* bp = g_Bf + wid * 32 + lane;

        #pragma unroll 4
        for (int s = 0; s < NSTEPC; s += 2) {
            {
                const int k0 = s * 8;
                const uint32_t a0 = __float_as_uint(ar0[k0 + q]);
                const uint32_t a1 = __float_as_uint(ar1[k0 + q]);
                const uint32_t a2 = __float_as_uint(ar0[k0 + q + 4]);
                const uint32_t a3 = __float_as_uint(ar1[k0 + q + 4]);
                const float2 b = bp[(size_t)s * 256];
                mma_tf32(ca, a0, a1, a2, a3,
                         __float_as_uint(b.x), __float_as_uint(b.y));
            }
            {
                const int k0 = (s + 1) * 8;
                const uint32_t a0 = __float_as_uint(ar0[k0 + q]);
                const uint32_t a1 = __float_as_uint(ar1[k0 + q]);
                const uint32_t a2 = __float_as_uint(ar0[k0 + q + 4]);
                const uint32_t a3 = __float_as_uint(ar1[k0 + q + 4]);
                const float2 b = bp[(size_t)(s + 1) * 256];
                mma_tf32(cb, a0, a1, a2, a3,
                         __float_as_uint(b.x), __float_as_uint(b.y));
            }
        }
        ca.x += cb.x; ca.y += cb.y; ca.z += cb.z; ca.w += cb.w;

        const float inv0 = inv_s[g4];
        const float inv1 = inv_s[g4 + 8];
        const int col = wid * 8 + 2 * q;
        *(float2*)(out + (size_t)(m0 + g4) * COUT + col) =
            make_float2(ca.x * inv0, ca.y * inv0);
        *(float2*)(out + (size_t)(m0 + g4 + 8) * COUT + col) =
            make_float2(ca.z * inv1, ca.w * inv1);
    }
}

// ================= launch =================
extern "C" void kernel_launch(void* const* d_in, const int* in_sizes, int n_in,
                              void* d_out, int out_size) {
    const float* qpts = nullptr;
    const float* spts = nullptr;
    const float* sfeats = nullptr;
    const void*  nbr = nullptr;
    const float* wts = nullptr;
    const float* kpts = nullptr;
    for (int i = 0; i < n_in; i++) {
        switch (in_sizes[i]) {
            case MQ * 3:        qpts   = (const float*)d_in[i]; break;
            case NSUP * 3:      spts   = (const float*)d_in[i]; break;
            case NSUP * CIN:    sfeats = (const float*)d_in[i]; break;
            case MQ * HN:       nbr    = d_in[i];               break;
            case KPN*CIN*COUT:  wts    = (const float*)d_in[i]; break;
            case KPN * 3:       kpts   = (const float*)d_in[i]; break;
            default: break;
        }
    }
    float* outp = (float*)d_out;

    cudaFuncSetAttribute(kpconv_kernel,
                         cudaFuncAttributeMaxDynamicSharedMemorySize, SMEM_BYTES);

    prep_kernel<<<FLAG_BLKS + BF_BLKS + 1, 256>>>(sfeats, wts, (const unsigned*)nbr);
    kpconv_kernel<<<MQ / MB, NTHR, SMEM_BYTES>>>(
        qpts, spts, nbr, kpts, outp);
}

// round 10
// speedup vs baseline: 1.5690x; 1.1021x over previous
#include <cuda_runtime.h>
#include <cstdint>

#define MQ     50000
#define NSUP   100000
#define HN     32
#define KPN    15
#define CIN    64
#define COUT   64
#define MB     16
#define NTHR   256
#define INFPT  1.0e6f

#define NSTEPC 128                // stage-C steps over 1024 permuted contraction dim
#define WT_KS  36                 // wT k-row stride (banks 4*g4+q distinct)
#define WT_MS  (16 * WT_KS)       // 576 per query (9216 words total; reused as red_s)
#define WGT_MS 1028               // wgt m-row stride (1024 + pad, 1028%32==4)
#define RED_WS 1056               // per-warp partial stride (8 nt * 132)

// smem words: wT/red 16*576 + wgt 16*1028 + kp 48 + inv 16 + idx 512
#define SMEM_WORDS (MB*WT_MS + MB*WGT_MS + 48 + MB + MB*HN)
#define SMEM_BYTES (SMEM_WORDS * 4)

__device__ int g_idx_is64;
__device__ unsigned char g_flags[NSUP];
__device__ float g_sfr[(size_t)NSUP * CIN];   // tf32-rounded sfeats
// pair-packed fragment W: g_Bf2[(step*4+ntp)*32+lane] = {b0(d0),b1(d0),b0(d1),b1(d1)}
__device__ float4 g_Bf2[NSTEPC * 4 * 32];

__device__ __forceinline__ float to_tf32(float x) {
    uint32_t r; asm("cvt.rna.tf32.f32 %0, %1;" : "=r"(r) : "f"(x));
    return __uint_as_float(r);
}
__device__ __forceinline__ void mma_tf32(float4& c, uint32_t a0, uint32_t a1,
                                         uint32_t a2, uint32_t a3,
                                         uint32_t b0, uint32_t b1) {
    asm volatile(
        "mma.sync.aligned.m16n8k8.row.col.f32.tf32.tf32.f32 "
        "{%0,%1,%2,%3}, {%4,%5,%6,%7}, {%8,%9}, {%0,%1,%2,%3};"
        : "+f"(c.x), "+f"(c.y), "+f"(c.z), "+f"(c.w)
        : "r"(a0), "r"(a1), "r"(a2), "r"(a3), "r"(b0), "r"(b1));
}

// permuted contraction index j -> W value (k<15 ? wts[k][c][d] : 0)
__device__ __forceinline__ float bf_val(const float* wts, int j, int d) {
    const int l    = (j >> 2) & 31;
    const int nt   = j >> 7;
    const int comp = j & 3;
    const int qq = l & 3;
    const int gg = l >> 2;
    const int k  = gg + ((comp >> 1) << 3);
    const int c  = (nt << 3) + (qq << 1) + (comp & 1);
    return (k < KPN) ? to_tf32(wts[(k * CIN + c) * COUT + d]) : 0.0f;
}

// ================= prep: flags + sfeats round + B pack + dtype detect ========
#define FLAG_BLKS ((NSUP + 7) / 8)
#define BF_BLKS   (NSTEPC * 4 * 32 / 256)    // 64
__global__ void __launch_bounds__(256) prep_kernel(const float* __restrict__ sfeats,
                                                   const float* __restrict__ wts,
                                                   const unsigned* __restrict__ nbr) {
    const int b = blockIdx.x;
    const int tid = threadIdx.x;

    if (b < FLAG_BLKS) {
        const int n = b * 8 + (tid >> 5);
        if (n >= NSUP) return;
        const int lane = tid & 31;
        const float* row = sfeats + (long long)n * CIN;
        const float v0 = row[lane];
        const float v1 = row[lane + 32];
        g_sfr[(size_t)n * CIN + lane]      = to_tf32(v0);
        g_sfr[(size_t)n * CIN + lane + 32] = to_tf32(v1);
        float s = v0 + v1;
        #pragma unroll
        for (int o = 16; o; o >>= 1) s += __shfl_xor_sync(0xffffffffu, s, o);
        if (lane == 0) g_flags[n] = (s > 0.0f) ? 1 : 0;
        return;
    }
    if (b < FLAG_BLKS + BF_BLKS) {
        const int e = (b - FLAG_BLKS) * 256 + tid;   // float4 index, < 16384
        const int lane = e & 31;
        const int ntp  = (e >> 5) & 3;
        const int step = e >> 7;              // 0..127
        const int q  = lane & 3;
        const int g4 = lane >> 2;
        const int d0 = (2 * ntp) * 8 + g4;
        const int d1 = d0 + 8;
        const int j0 = step * 8 + q;
        g_Bf2[e] = make_float4(bf_val(wts, j0, d0), bf_val(wts, j0 + 4, d0),
                               bf_val(wts, j0, d1), bf_val(wts, j0 + 4, d1));
        return;
    }
    if (tid == 0) {
        int is64 = 1;
        #pragma unroll
        for (int i = 0; i < 64; i++) {
            if (nbr[2 * i + 1] != 0u) { is64 = 0; break; }
        }
        g_idx_is64 = is64;
    }
}

// ================= fused main kernel =================
extern "C" __global__ void __launch_bounds__(NTHR, 2)
kpconv_kernel(const float* __restrict__ qpts,
              const float* __restrict__ spts,
              const void*  __restrict__ nbr,
              const float* __restrict__ kpts,
              float* __restrict__ out)
{
    extern __shared__ float sm[];
    float* wT_s  = sm;                          // [MB][16][WT_KS]; later red_s
    float* red_s = sm;                          // [8][RED_WS] partials (reuse)
    float* wgt_s = sm + MB * WT_MS;             // [MB][WGT_MS] fragment-order wgt
    float* kp_s  = wgt_s + MB * WGT_MS;         // 48
    float* inv_s = kp_s + 48;                   // MB
    int*   idx_s = (int*)(inv_s + MB);          // [MB][HN]

    const int tid = threadIdx.x;
    const int m0  = blockIdx.x * MB;
    const bool is64 = (g_idx_is64 != 0);

    const int wid  = tid >> 5;
    const int lane = tid & 31;
    const int q    = lane & 3;
    const int g4   = lane >> 2;

    if (tid < KPN * 3) kp_s[tid] = kpts[tid];
    __syncthreads();

    // ---------------- Stage A: w[m,h,k] -> wT_s (tf32, transposed) ----------
    #pragma unroll
    for (int it = 0; it < 2; it++) {
        const int p = tid + it * NTHR;          // p < MB*HN = 512
        const int m = p >> 5;
        const int h = p & 31;
        const long long gi = (long long)(m0 + m) * HN + h;
        int idx;
        if (is64) idx = (int)((const long long*)nbr)[gi];
        else      idx = ((const int*)nbr)[gi];
        const bool valid = (idx < NSUP);

        float px, py, pz;
        if (valid) {
            const float* s3 = spts + (long long)idx * 3;
            px = s3[0]; py = s3[1]; pz = s3[2];
        } else {
            px = INFPT; py = INFPT; pz = INFPT;
        }
        const float* q3 = qpts + (long long)(m0 + m) * 3;
        const float rx = px - q3[0];
        const float ry = py - q3[1];
        const float rz = pz - q3[2];

        float* wcol = wT_s + m * WT_MS;
        float wmax = 0.0f;
        #pragma unroll
        for (int k = 0; k < KPN; k++) {
            const float dx = rx - kp_s[k * 3 + 0];
            const float dy = ry - kp_s[k * 3 + 1];
            const float dz = rz - kp_s[k * 3 + 2];
            const float sq = dx * dx + dy * dy + dz * dz;
            const float w  = fmaxf(1.0f - sqrtf(sq) * 0.5f, 0.0f);
            wcol[k * WT_KS + h] = to_tf32(w);
            wmax = fmaxf(wmax, w);
        }
        wcol[15 * WT_KS + h] = 0.0f;            // zero pad k-row

        bool real = false;
        if (valid) real = (g_flags[idx] != 0);
        const unsigned bal = __ballot_sync(0xffffffffu, real);
        if ((tid & 31) == 0) inv_s[m] = 1.0f / (float)max(__popc(bal), 1);

        idx_s[p] = (wmax > 0.0f) ? idx : -1;
    }
    __syncthreads();

    // ---------------- Stage B (mma, warp-private, no barriers) --------------
    {
        #pragma unroll
        for (int half = 0; half < 2; half++) {
            const int mq = 2 * wid + half;
            const int*   irow = idx_s + mq * HN;
            const float* wtm  = wT_s + mq * WT_MS;

            float4 acc[8];
            #pragma unroll
            for (int nt = 0; nt < 8; nt++) acc[nt] = make_float4(0.f, 0.f, 0.f, 0.f);

            #pragma unroll
            for (int s = 0; s < 4; s++) {
                const int h0 = s * 8;
                const uint32_t a0 = __float_as_uint(wtm[g4 * WT_KS + h0 + q]);
                const uint32_t a1 = __float_as_uint(wtm[(g4 + 8) * WT_KS + h0 + q]);
                const uint32_t a2 = __float_as_uint(wtm[g4 * WT_KS + h0 + q + 4]);
                const uint32_t a3 = __float_as_uint(wtm[(g4 + 8) * WT_KS + h0 + q + 4]);
                const int i0 = irow[h0 + q];
                const int i1 = irow[h0 + q + 4];
                const bool v0 = (i0 >= 0);
                const bool v1 = (i1 >= 0);
                const float* p0 = g_sfr + (size_t)(v0 ? i0 : 0) * CIN + g4;
                const float* p1 = g_sfr + (size_t)(v1 ? i1 : 0) * CIN + g4;
                #pragma unroll
                for (int nt = 0; nt < 8; nt++) {
                    const float b0 = v0 ? p0[nt * 8] : 0.0f;
                    const float b1 = v1 ? p1[nt * 8] : 0.0f;
                    mma_tf32(acc[nt], a0, a1, a2, a3,
                             __float_as_uint(b0), __float_as_uint(b1));
                }
            }

            // fragment-native epilogue: word j = nt*128 + lane*4 + comp
            float* wq = wgt_s + mq * WGT_MS;
            #pragma unroll
            for (int nt = 0; nt < 8; nt++) {
                *(float4*)(wq + nt * 128 + lane * 4) =
                    make_float4(to_tf32(acc[nt].x), to_tf32(acc[nt].y),
                                to_tf32(acc[nt].z), to_tf32(acc[nt].w));
            }
        }
    }
    __syncthreads();

    // ---------------- Stage C (mma, warp-sliced contraction) ----------------
    // warp wid handles steps [16*wid, 16*wid+16) for ALL 8 n-tiles
    {
        float4 acc[8];
        #pragma unroll
        for (int nt = 0; nt < 8; nt++) acc[nt] = make_float4(0.f, 0.f, 0.f, 0.f);

        const float* ar0 = wgt_s + g4 * WGT_MS;
        const float* ar1 = wgt_s + (g4 + 8) * WGT_MS;

        #pragma unroll 4
        for (int ss = 0; ss < 16; ss++) {
            const int s  = wid * 16 + ss;
            const int k0 = s * 8;
            const uint32_t a0 = __float_as_uint(ar0[k0 + q]);
            const uint32_t a1 = __float_as_uint(ar1[k0 + q]);
            const uint32_t a2 = __float_as_uint(ar0[k0 + q + 4]);
            const uint32_t a3 = __float_as_uint(ar1[k0 + q + 4]);
            const float4* bp = g_Bf2 + (size_t)(s * 4) * 32 + lane;
            #pragma unroll
            for (int ntp = 0; ntp < 4; ntp++) {
                const float4 b = bp[ntp * 32];
                mma_tf32(acc[2 * ntp],     a0, a1, a2, a3,
                         __float_as_uint(b.x), __float_as_uint(b.y));
                mma_tf32(acc[2 * ntp + 1], a0, a1, a2, a3,
                         __float_as_uint(b.z), __float_as_uint(b.w));
            }
        }

        // write fragment-native partials (wT region is dead now)
        float* rw = red_s + wid * RED_WS;
        #pragma unroll
        for (int nt = 0; nt < 8; nt++) {
            *(float4*)(rw + nt * 132 + lane * 4) = acc[nt];
        }
    }
    __syncthreads();

    // ---------------- final: sum 8 warp-partials, scale, store --------------
    {
        const int m  = tid >> 4;          // 0..15
        const int e  = tid & 15;          // d0 = 4e
        const int nt = e >> 1;
        const int q0 = 2 * (e & 1);
        const int g4m = m & 7;
        const int up  = m >> 3;
        const int off0 = nt * 132 + (g4m * 4 + q0) * 4 + 2 * up;
        const int off1 = off0 + 4;        // q0+1

        float2 s0 = make_float2(0.f, 0.f);
        float2 s1 = make_float2(0.f, 0.f);
        #pragma unroll
        for (int w = 0; w < 8; w++) {
            const float* rp = red_s + w * RED_WS;
            const float2 p0 = *(const float2*)(rp + off0);
            const float2 p1 = *(const float2*)(rp + off1);
            s0.x += p0.x; s0.y += p0.y;
            s1.x += p1.x; s1.y += p1.y;
        }
        const float inv = inv_s[m];
        *(float4*)(out + (size_t)(m0 + m) * COUT + 4 * e) =
            make_float4(s0.x * inv, s0.y * inv, s1.x * inv, s1.y * inv);
    }
}

// ================= launch =================
extern "C" void kernel_launch(void* const* d_in, const int* in_sizes, int n_in,
                              void* d_out, int out_size) {
    const float* qpts = nullptr;
    const float* spts = nullptr;
    const float* sfeats = nullptr;
    const void*  nbr = nullptr;
    const float* wts = nullptr;
    const float* kpts = nullptr;
    for (int i = 0; i < n_in; i++) {
        switch (in_sizes[i]) {
            case MQ * 3:        qpts   = (const float*)d_in[i]; break;
            case NSUP * 3:      spts   = (const float*)d_in[i]; break;
            case NSUP * CIN:    sfeats = (const float*)d_in[i]; break;
            case MQ * HN:       nbr    = d_in[i];               break;
            case KPN*CIN*COUT:  wts    = (const float*)d_in[i]; break;
            case KPN * 3:       kpts   = (const float*)d_in[i]; break;
            default: break;
        }
    }
    float* outp = (float*)d_out;

    cudaFuncSetAttribute(kpconv_kernel,
                         cudaFuncAttributeMaxDynamicSharedMemorySize, SMEM_BYTES);

    prep_kernel<<<FLAG_BLKS + BF_BLKS + 1, 256>>>(sfeats, wts, (const unsigned*)nbr);
    kpconv_kernel<<<MQ / MB, NTHR, SMEM_BYTES>>>(
        qpts, spts, nbr, kpts, outp);
}

// round 11
// speedup vs baseline: 1.6469x; 1.0496x over previous
#include <cuda_runtime.h>
#include <cstdint>

#define MQ     50000
#define NSUP   100000
#define HN     32
#define KPN    15
#define CIN    64
#define COUT   64
#define MB     16
#define NTHR   256
#define INFPT  1.0e6f

#define NSTEPC 128                // stage-C steps over 1024 permuted contraction dim
#define WT_KS  36                 // wT k-row stride (banks 4*g4+q distinct)
#define WT_MS  (16 * WT_KS)       // 576 per query (9216 words total; reused as red_s)
#define WGT_MS 1028               // wgt m-row stride (1024 + pad, 1028%32==4)
#define RED_WS 1056               // per-warp partial stride (8 nt * 132)

// smem words: wT/red 16*576 + wgt 16*1028 + kp 48 + inv 16 + idx 512
#define SMEM_WORDS (MB*WT_MS + MB*WGT_MS + 48 + MB + MB*HN)
#define SMEM_BYTES (SMEM_WORDS * 4)

__device__ int g_idx_is64;
__device__ unsigned char g_flags[NSUP];
__device__ float g_sfr[(size_t)NSUP * CIN];   // tf32-rounded sfeats
// pair-packed fragment W: g_Bf2[(step*4+ntp)*32+lane] = {b0(d0),b1(d0),b0(d1),b1(d1)}
__device__ float4 g_Bf2[NSTEPC * 4 * 32];

__device__ __forceinline__ float to_tf32(float x) {
    uint32_t r; asm("cvt.rna.tf32.f32 %0, %1;" : "=r"(r) : "f"(x));
    return __uint_as_float(r);
}
// sqrt on the FMA pipe: bit-hack rsqrt + 2 Newton iterations, d = sq * rsqrt(sq).
// Zero MUFU. rel err ~4.4e-6. sq must be > 0 (caller guards with fmaxf).
__device__ __forceinline__ float fastsqrt(float sq) {
    float y = __uint_as_float(0x5f3759dfu - (__float_as_uint(sq) >> 1));
    const float nh = -0.5f * sq;
    y = y * fmaf(nh, y * y, 1.5f);
    y = y * fmaf(nh, y * y, 1.5f);
    return sq * y;
}
__device__ __forceinline__ void mma_tf32(float4& c, uint32_t a0, uint32_t a1,
                                         uint32_t a2, uint32_t a3,
                                         uint32_t b0, uint32_t b1) {
    asm volatile(
        "mma.sync.aligned.m16n8k8.row.col.f32.tf32.tf32.f32 "
        "{%0,%1,%2,%3}, {%4,%5,%6,%7}, {%8,%9}, {%0,%1,%2,%3};"
        : "+f"(c.x), "+f"(c.y), "+f"(c.z), "+f"(c.w)
        : "r"(a0), "r"(a1), "r"(a2), "r"(a3), "r"(b0), "r"(b1));
}

// permuted contraction index j -> W value (k<15 ? wts[k][c][d] : 0)
__device__ __forceinline__ float bf_val(const float* wts, int j, int d) {
    const int l    = (j >> 2) & 31;
    const int nt   = j >> 7;
    const int comp = j & 3;
    const int qq = l & 3;
    const int gg = l >> 2;
    const int k  = gg + ((comp >> 1) << 3);
    const int c  = (nt << 3) + (qq << 1) + (comp & 1);
    return (k < KPN) ? to_tf32(wts[(k * CIN + c) * COUT + d]) : 0.0f;
}

// ================= prep: flags + sfeats round + B pack + dtype detect ========
#define FLAG_BLKS ((NSUP + 7) / 8)
#define BF_BLKS   (NSTEPC * 4 * 32 / 256)    // 64
__global__ void __launch_bounds__(256) prep_kernel(const float* __restrict__ sfeats,
                                                   const float* __restrict__ wts,
                                                   const unsigned* __restrict__ nbr) {
    const int b = blockIdx.x;
    const int tid = threadIdx.x;

    if (b < FLAG_BLKS) {
        const int n = b * 8 + (tid >> 5);
        if (n >= NSUP) return;
        const int lane = tid & 31;
        const float* row = sfeats + (long long)n * CIN;
        const float v0 = row[lane];
        const float v1 = row[lane + 32];
        g_sfr[(size_t)n * CIN + lane]      = to_tf32(v0);
        g_sfr[(size_t)n * CIN + lane + 32] = to_tf32(v1);
        float s = v0 + v1;
        #pragma unroll
        for (int o = 16; o; o >>= 1) s += __shfl_xor_sync(0xffffffffu, s, o);
        if (lane == 0) g_flags[n] = (s > 0.0f) ? 1 : 0;
        return;
    }
    if (b < FLAG_BLKS + BF_BLKS) {
        const int e = (b - FLAG_BLKS) * 256 + tid;   // float4 index, < 16384
        const int lane = e & 31;
        const int ntp  = (e >> 5) & 3;
        const int step = e >> 7;              // 0..127
        const int q  = lane & 3;
        const int g4 = lane >> 2;
        const int d0 = (2 * ntp) * 8 + g4;
        const int d1 = d0 + 8;
        const int j0 = step * 8 + q;
        g_Bf2[e] = make_float4(bf_val(wts, j0, d0), bf_val(wts, j0 + 4, d0),
                               bf_val(wts, j0, d1), bf_val(wts, j0 + 4, d1));
        return;
    }
    if (tid == 0) {
        int is64 = 1;
        #pragma unroll
        for (int i = 0; i < 64; i++) {
            if (nbr[2 * i + 1] != 0u) { is64 = 0; break; }
        }
        g_idx_is64 = is64;
    }
}

// ================= fused main kernel =================
extern "C" __global__ void __launch_bounds__(NTHR, 2)
kpconv_kernel(const float* __restrict__ qpts,
              const float* __restrict__ spts,
              const void*  __restrict__ nbr,
              const float* __restrict__ kpts,
              float* __restrict__ out)
{
    extern __shared__ float sm[];
    float* wT_s  = sm;                          // [MB][16][WT_KS]; later red_s
    float* red_s = sm;                          // [8][RED_WS] partials (reuse)
    float* wgt_s = sm + MB * WT_MS;             // [MB][WGT_MS] fragment-order wgt
    float* kp_s  = wgt_s + MB * WGT_MS;         // 48
    float* inv_s = kp_s + 48;                   // MB
    int*   idx_s = (int*)(inv_s + MB);          // [MB][HN]

    const int tid = threadIdx.x;
    const int m0  = blockIdx.x * MB;
    const bool is64 = (g_idx_is64 != 0);

    const int wid  = tid >> 5;
    const int lane = tid & 31;
    const int q    = lane & 3;
    const int g4   = lane >> 2;

    if (tid < KPN * 3) kp_s[tid] = kpts[tid];
    __syncthreads();

    // ---------------- Stage A: w[m,h,k] -> wT_s (tf32, transposed) ----------
    #pragma unroll
    for (int it = 0; it < 2; it++) {
        const int p = tid + it * NTHR;          // p < MB*HN = 512
        const int m = p >> 5;
        const int h = p & 31;
        const long long gi = (long long)(m0 + m) * HN + h;
        int idx;
        if (is64) idx = (int)((const long long*)nbr)[gi];
        else      idx = ((const int*)nbr)[gi];
        const bool valid = (idx < NSUP);

        float px, py, pz;
        if (valid) {
            const float* s3 = spts + (long long)idx * 3;
            px = s3[0]; py = s3[1]; pz = s3[2];
        } else {
            px = INFPT; py = INFPT; pz = INFPT;
        }
        const float* q3 = qpts + (long long)(m0 + m) * 3;
        const float rx = px - q3[0];
        const float ry = py - q3[1];
        const float rz = pz - q3[2];

        float* wcol = wT_s + m * WT_MS;
        float wmax = 0.0f;
        #pragma unroll
        for (int k = 0; k < KPN; k++) {
            const float dx = rx - kp_s[k * 3 + 0];
            const float dy = ry - kp_s[k * 3 + 1];
            const float dz = rz - kp_s[k * 3 + 2];
            const float sq = fmaxf(dx * dx + dy * dy + dz * dz, 1e-12f);
            const float w  = fmaxf(fmaf(fastsqrt(sq), -0.5f, 1.0f), 0.0f);
            wcol[k * WT_KS + h] = to_tf32(w);
            wmax = fmaxf(wmax, w);
        }
        wcol[15 * WT_KS + h] = 0.0f;            // zero pad k-row

        bool real = false;
        if (valid) real = (g_flags[idx] != 0);
        const unsigned bal = __ballot_sync(0xffffffffu, real);
        if ((tid & 31) == 0) inv_s[m] = 1.0f / (float)max(__popc(bal), 1);

        idx_s[p] = (wmax > 0.0f) ? idx : -1;
    }
    __syncthreads();

    // ---------------- Stage B (mma, warp-private, no barriers) --------------
    {
        #pragma unroll
        for (int half = 0; half < 2; half++) {
            const int mq = 2 * wid + half;
            const int*   irow = idx_s + mq * HN;
            const float* wtm  = wT_s + mq * WT_MS;

            float4 acc[8];
            #pragma unroll
            for (int nt = 0; nt < 8; nt++) acc[nt] = make_float4(0.f, 0.f, 0.f, 0.f);

            #pragma unroll
            for (int s = 0; s < 4; s++) {
                const int h0 = s * 8;
                const uint32_t a0 = __float_as_uint(wtm[g4 * WT_KS + h0 + q]);
                const uint32_t a1 = __float_as_uint(wtm[(g4 + 8) * WT_KS + h0 + q]);
                const uint32_t a2 = __float_as_uint(wtm[g4 * WT_KS + h0 + q + 4]);
                const uint32_t a3 = __float_as_uint(wtm[(g4 + 8) * WT_KS + h0 + q + 4]);
                const int i0 = irow[h0 + q];
                const int i1 = irow[h0 + q + 4];
                const bool v0 = (i0 >= 0);
                const bool v1 = (i1 >= 0);
                const float* p0 = g_sfr + (size_t)(v0 ? i0 : 0) * CIN + g4;
                const float* p1 = g_sfr + (size_t)(v1 ? i1 : 0) * CIN + g4;
                #pragma unroll
                for (int nt = 0; nt < 8; nt++) {
                    const float b0 = v0 ? p0[nt * 8] : 0.0f;
                    const float b1 = v1 ? p1[nt * 8] : 0.0f;
                    mma_tf32(acc[nt], a0, a1, a2, a3,
                             __float_as_uint(b0), __float_as_uint(b1));
                }
            }

            // fragment-native epilogue: word j = nt*128 + lane*4 + comp
            float* wq = wgt_s + mq * WGT_MS;
            #pragma unroll
            for (int nt = 0; nt < 8; nt++) {
                *(float4*)(wq + nt * 128 + lane * 4) =
                    make_float4(to_tf32(acc[nt].x), to_tf32(acc[nt].y),
                                to_tf32(acc[nt].z), to_tf32(acc[nt].w));
            }
        }
    }
    __syncthreads();

    // ---------------- Stage C (mma, warp-sliced contraction) ----------------
    // warp wid handles steps [16*wid, 16*wid+16) for ALL 8 n-tiles
    {
        float4 acc[8];
        #pragma unroll
        for (int nt = 0; nt < 8; nt++) acc[nt] = make_float4(0.f, 0.f, 0.f, 0.f);

        const float* ar0 = wgt_s + g4 * WGT_MS;
        const float* ar1 = wgt_s + (g4 + 8) * WGT_MS;

        #pragma unroll 4
        for (int ss = 0; ss < 16; ss++) {
            const int s  = wid * 16 + ss;
            const int k0 = s * 8;
            const uint32_t a0 = __float_as_uint(ar0[k0 + q]);
            const uint32_t a1 = __float_as_uint(ar1[k0 + q]);
            const uint32_t a2 = __float_as_uint(ar0[k0 + q + 4]);
            const uint32_t a3 = __float_as_uint(ar1[k0 + q + 4]);
            const float4* bp = g_Bf2 + (size_t)(s * 4) * 32 + lane;
            #pragma unroll
            for (int ntp = 0; ntp < 4; ntp++) {
                const float4 b = bp[ntp * 32];
                mma_tf32(acc[2 * ntp],     a0, a1, a2, a3,
                         __float_as_uint(b.x), __float_as_uint(b.y));
                mma_tf32(acc[2 * ntp + 1], a0, a1, a2, a3,
                         __float_as_uint(b.z), __float_as_uint(b.w));
            }
        }

        // write fragment-native partials (wT region is dead now)
        float* rw = red_s + wid * RED_WS;
        #pragma unroll
        for (int nt = 0; nt < 8; nt++) {
            *(float4*)(rw + nt * 132 + lane * 4) = acc[nt];
        }
    }
    __syncthreads();

    // ---------------- final: sum 8 warp-partials, scale, store --------------
    {
        const int m  = tid >> 4;          // 0..15
        const int e  = tid & 15;          // d0 = 4e
        const int nt = e >> 1;
        const int q0 = 2 * (e & 1);
        const int g4m = m & 7;
        const int up  = m >> 3;
        const int off0 = nt * 132 + (g4m * 4 + q0) * 4 + 2 * up;
        const int off1 = off0 + 4;        // q0+1

        float2 s0 = make_float2(0.f, 0.f);
        float2 s1 = make_float2(0.f, 0.f);
        #pragma unroll
        for (int w = 0; w < 8; w++) {
            const float* rp = red_s + w * RED_WS;
            const float2 p0 = *(const float2*)(rp + off0);
            const float2 p1 = *(const float2*)(rp + off1);
            s0.x += p0.x; s0.y += p0.y;
            s1.x += p1.x; s1.y += p1.y;
        }
        const float inv = inv_s[m];
        *(float4*)(out + (size_t)(m0 + m) * COUT + 4 * e) =
            make_float4(s0.x * inv, s0.y * inv, s1.x * inv, s1.y * inv);
    }
}

// ================= launch =================
extern "C" void kernel_launch(void* const* d_in, const int* in_sizes, int n_in,
                              void* d_out, int out_size) {
    const float* qpts = nullptr;
    const float* spts = nullptr;
    const float* sfeats = nullptr;
    const void*  nbr = nullptr;
    const float* wts = nullptr;
    const float* kpts = nullptr;
    for (int i = 0; i < n_in; i++) {
        switch (in_sizes[i]) {
            case MQ * 3:        qpts   = (const float*)d_in[i]; break;
            case NSUP * 3:      spts   = (const float*)d_in[i]; break;
            case NSUP * CIN:    sfeats = (const float*)d_in[i]; break;
            case MQ * HN:       nbr    = d_in[i];               break;
            case KPN*CIN*COUT:  wts    = (const float*)d_in[i]; break;
            case KPN * 3:       kpts   = (const float*)d_in[i]; break;
            default: break;
        }
    }
    float* outp = (float*)d_out;

    cudaFuncSetAttribute(kpconv_kernel,
                         cudaFuncAttributeMaxDynamicSharedMemorySize, SMEM_BYTES);

    prep_kernel<<<FLAG_BLKS + BF_BLKS + 1, 256>>>(sfeats, wts, (const unsigned*)nbr);
    kpconv_kernel<<<MQ / MB, NTHR, SMEM_BYTES>>>(
        qpts, spts, nbr, kpts, outp);
}

// round 12
// speedup vs baseline: 1.7350x; 1.0536x over previous
#include <cuda_runtime.h>
#include <cstdint>

#define MQ     50000
#define NSUP   100000
#define HN     32
#define KPN    15
#define CIN    64
#define COUT   64
#define MB     16
#define NTHR   256
#define INFPT  1.0e6f

#define NSTEPC 128                // stage-C steps over 1024 permuted contraction dim
#define WT_KS  36                 // wT k-row stride inside slab (banks 4*g4+q distinct)
#define SLAB   1028               // per-query slab: wT[0..575] then wgt[0..1023] (+pad)
#define RED_WS 1056               // per-warp partial stride (8 nt * 132)

// smem words: slabs 16*1028 + kp4 64 + inv 16 + idx 512
#define SMEM_WORDS (MB*SLAB + 64 + MB + MB*HN)
#define SMEM_BYTES (SMEM_WORDS * 4)

__device__ int g_idx_is64;
__device__ unsigned char g_flags[NSUP];
__device__ float g_sfr[(size_t)NSUP * CIN];   // tf32-rounded sfeats
// pair-packed fragment W: g_Bf2[(step*4+ntp)*32+lane] = {b0(d0),b1(d0),b0(d1),b1(d1)}
__device__ float4 g_Bf2[NSTEPC * 4 * 32];

__device__ __forceinline__ float to_tf32(float x) {
    uint32_t r; asm("cvt.rna.tf32.f32 %0, %1;" : "=r"(r) : "f"(x));
    return __uint_as_float(r);
}
// sqrt on the FMA pipe: bit-hack rsqrt + 2 Newton iterations. Zero MUFU.
__device__ __forceinline__ float fastsqrt(float sq) {
    float y = __uint_as_float(0x5f3759dfu - (__float_as_uint(sq) >> 1));
    const float nh = -0.5f * sq;
    y = y * fmaf(nh, y * y, 1.5f);
    y = y * fmaf(nh, y * y, 1.5f);
    return sq * y;
}
__device__ __forceinline__ void mma_tf32(float4& c, uint32_t a0, uint32_t a1,
                                         uint32_t a2, uint32_t a3,
                                         uint32_t b0, uint32_t b1) {
    asm volatile(
        "mma.sync.aligned.m16n8k8.row.col.f32.tf32.tf32.f32 "
        "{%0,%1,%2,%3}, {%4,%5,%6,%7}, {%8,%9}, {%0,%1,%2,%3};"
        : "+f"(c.x), "+f"(c.y), "+f"(c.z), "+f"(c.w)
        : "r"(a0), "r"(a1), "r"(a2), "r"(a3), "r"(b0), "r"(b1));
}

// permuted contraction index j -> W value (k<15 ? wts[k][c][d] : 0)
__device__ __forceinline__ float bf_val(const float* wts, int j, int d) {
    const int l    = (j >> 2) & 31;
    const int nt   = j >> 7;
    const int comp = j & 3;
    const int qq = l & 3;
    const int gg = l >> 2;
    const int k  = gg + ((comp >> 1) << 3);
    const int c  = (nt << 3) + (qq << 1) + (comp & 1);
    return (k < KPN) ? to_tf32(wts[(k * CIN + c) * COUT + d]) : 0.0f;
}

// ================= prep: flags + sfeats round + B pack + dtype detect ========
#define FLAG_BLKS ((NSUP + 7) / 8)
#define BF_BLKS   (NSTEPC * 4 * 32 / 256)    // 64
__global__ void __launch_bounds__(256) prep_kernel(const float* __restrict__ sfeats,
                                                   const float* __restrict__ wts,
                                                   const unsigned* __restrict__ nbr) {
    const int b = blockIdx.x;
    const int tid = threadIdx.x;

    if (b < FLAG_BLKS) {
        const int n = b * 8 + (tid >> 5);
        if (n >= NSUP) return;
        const int lane = tid & 31;
        const float* row = sfeats + (long long)n * CIN;
        const float v0 = row[lane];
        const float v1 = row[lane + 32];
        g_sfr[(size_t)n * CIN + lane]      = to_tf32(v0);
        g_sfr[(size_t)n * CIN + lane + 32] = to_tf32(v1);
        float s = v0 + v1;
        #pragma unroll
        for (int o = 16; o; o >>= 1) s += __shfl_xor_sync(0xffffffffu, s, o);
        if (lane == 0) g_flags[n] = (s > 0.0f) ? 1 : 0;
        return;
    }
    if (b < FLAG_BLKS + BF_BLKS) {
        const int e = (b - FLAG_BLKS) * 256 + tid;   // float4 index, < 16384
        const int lane = e & 31;
        const int ntp  = (e >> 5) & 3;
        const int step = e >> 7;              // 0..127
        const int q  = lane & 3;
        const int g4 = lane >> 2;
        const int d0 = (2 * ntp) * 8 + g4;
        const int d1 = d0 + 8;
        const int j0 = step * 8 + q;
        g_Bf2[e] = make_float4(bf_val(wts, j0, d0), bf_val(wts, j0 + 4, d0),
                               bf_val(wts, j0, d1), bf_val(wts, j0 + 4, d1));
        return;
    }
    if (tid == 0) {
        int is64 = 1;
        #pragma unroll
        for (int i = 0; i < 64; i++) {
            if (nbr[2 * i + 1] != 0u) { is64 = 0; break; }
        }
        g_idx_is64 = is64;
    }
}

// ================= fused main kernel =================
extern "C" __global__ void __launch_bounds__(NTHR, 3)
kpconv_kernel(const float* __restrict__ qpts,
              const float* __restrict__ spts,
              const void*  __restrict__ nbr,
              const float* __restrict__ kpts,
              float* __restrict__ out)
{
    extern __shared__ float sm[];
    float* slab_s = sm;                         // [MB][SLAB]: wT -> wgt -> red
    float* red_s  = sm;                         // [8][RED_WS] (after wgt dead)
    float* kp4_s  = sm + MB * SLAB;             // [15][4] = {x,y,z,|kp|^2}
    float* inv_s  = kp4_s + 64;                 // MB
    int*   idx_s  = (int*)(inv_s + MB);         // [MB][HN]

    const int tid = threadIdx.x;
    const int m0  = blockIdx.x * MB;
    const bool is64 = (g_idx_is64 != 0);

    const int wid  = tid >> 5;
    const int lane = tid & 31;
    const int q    = lane & 3;
    const int g4   = lane >> 2;

    if (tid < KPN) {
        const float kx = kpts[3 * tid + 0];
        const float ky = kpts[3 * tid + 1];
        const float kz = kpts[3 * tid + 2];
        *(float4*)(kp4_s + 4 * tid) =
            make_float4(kx, ky, kz, fmaf(kx, kx, fmaf(ky, ky, kz * kz)));
    }
    __syncthreads();

    // ---------------- Stage A: w[m,h,k] -> slab wT (tf32, transposed) -------
    #pragma unroll
    for (int it = 0; it < 2; it++) {
        const int p = tid + it * NTHR;          // p < MB*HN = 512
        const int m = p >> 5;
        const int h = p & 31;
        const long long gi = (long long)(m0 + m) * HN + h;
        int idx;
        if (is64) idx = (int)((const long long*)nbr)[gi];
        else      idx = ((const int*)nbr)[gi];
        const bool valid = (idx < NSUP);

        float px, py, pz;
        if (valid) {
            const float* s3 = spts + (long long)idx * 3;
            px = s3[0]; py = s3[1]; pz = s3[2];
        } else {
            px = INFPT; py = INFPT; pz = INFPT;
        }
        const float* q3 = qpts + (long long)(m0 + m) * 3;
        const float rx = px - q3[0];
        const float ry = py - q3[1];
        const float rz = pz - q3[2];
        const float rr  = fmaf(rx, rx, fmaf(ry, ry, rz * rz));
        const float m2x = -2.0f * rx;
        const float m2y = -2.0f * ry;
        const float m2z = -2.0f * rz;

        float* wcol = slab_s + m * SLAB;        // wT region [0, 576)
        float wmax = 0.0f;
        #pragma unroll
        for (int k = 0; k < KPN; k++) {
            const float4 kp = *(const float4*)(kp4_s + 4 * k);
            const float sq0 = fmaf(m2x, kp.x,
                              fmaf(m2y, kp.y,
                              fmaf(m2z, kp.z, rr + kp.w)));
            const float sq = fmaxf(sq0, 1e-12f);
            const float w  = fmaxf(fmaf(fastsqrt(sq), -0.5f, 1.0f), 0.0f);
            wcol[k * WT_KS + h] = to_tf32(w);
            wmax = fmaxf(wmax, w);
        }
        wcol[15 * WT_KS + h] = 0.0f;            // zero pad k-row

        bool real = false;
        if (valid) real = (g_flags[idx] != 0);
        const unsigned bal = __ballot_sync(0xffffffffu, real);
        if ((tid & 31) == 0) inv_s[m] = 1.0f / (float)max(__popc(bal), 1);

        idx_s[p] = (wmax > 0.0f) ? idx : -1;
    }
    __syncthreads();

    // ---------------- Stage B (mma, warp-private): wgt = wT @ f -------------
    // warp wid owns queries 2*wid, 2*wid+1: reads ONLY its own slabs' wT,
    // writes ONLY its own slabs' wgt (after all its wT reads) -> no race.
    {
        #pragma unroll
        for (int half = 0; half < 2; half++) {
            const int mq = 2 * wid + half;
            const int*   irow = idx_s + mq * HN;
            const float* wtm  = slab_s + mq * SLAB;

            float4 acc[8];
            #pragma unroll
            for (int nt = 0; nt < 8; nt++) acc[nt] = make_float4(0.f, 0.f, 0.f, 0.f);

            #pragma unroll
            for (int s = 0; s < 4; s++) {
                const int h0 = s * 8;
                const uint32_t a0 = __float_as_uint(wtm[g4 * WT_KS + h0 + q]);
                const uint32_t a1 = __float_as_uint(wtm[(g4 + 8) * WT_KS + h0 + q]);
                const uint32_t a2 = __float_as_uint(wtm[g4 * WT_KS + h0 + q + 4]);
                const uint32_t a3 = __float_as_uint(wtm[(g4 + 8) * WT_KS + h0 + q + 4]);
                const int i0 = irow[h0 + q];
                const int i1 = irow[h0 + q + 4];
                const bool v0 = (i0 >= 0);
                const bool v1 = (i1 >= 0);
                const float* p0 = g_sfr + (size_t)(v0 ? i0 : 0) * CIN + g4;
                const float* p1 = g_sfr + (size_t)(v1 ? i1 : 0) * CIN + g4;
                #pragma unroll
                for (int nt = 0; nt < 8; nt++) {
                    const float b0 = v0 ? p0[nt * 8] : 0.0f;
                    const float b1 = v1 ? p1[nt * 8] : 0.0f;
                    mma_tf32(acc[nt], a0, a1, a2, a3,
                             __float_as_uint(b0), __float_as_uint(b1));
                }
            }

            // fragment-native epilogue overwrites this query's slab (wT dead)
            float* wq = slab_s + mq * SLAB;
            #pragma unroll
            for (int nt = 0; nt < 8; nt++) {
                *(float4*)(wq + nt * 128 + lane * 4) =
                    make_float4(to_tf32(acc[nt].x), to_tf32(acc[nt].y),
                                to_tf32(acc[nt].z), to_tf32(acc[nt].w));
            }
        }
    }
    __syncthreads();

    // ---------------- Stage C (mma, warp-sliced contraction) ----------------
    // warp wid handles steps [16*wid, 16*wid+16) for ALL 8 n-tiles
    {
        float4 acc[8];
        #pragma unroll
        for (int nt = 0; nt < 8; nt++) acc[nt] = make_float4(0.f, 0.f, 0.f, 0.f);

        const float* ar0 = slab_s + g4 * SLAB;
        const float* ar1 = slab_s + (g4 + 8) * SLAB;

        #pragma unroll 4
        for (int ss = 0; ss < 16; ss++) {
            const int s  = wid * 16 + ss;
            const int k0 = s * 8;
            const uint32_t a0 = __float_as_uint(ar0[k0 + q]);
            const uint32_t a1 = __float_as_uint(ar1[k0 + q]);
            const uint32_t a2 = __float_as_uint(ar0[k0 + q + 4]);
            const uint32_t a3 = __float_as_uint(ar1[k0 + q + 4]);
            const float4* bp = g_Bf2 + (size_t)(s * 4) * 32 + lane;
            #pragma unroll
            for (int ntp = 0; ntp < 4; ntp++) {
                const float4 b = bp[ntp * 32];
                mma_tf32(acc[2 * ntp],     a0, a1, a2, a3,
                         __float_as_uint(b.x), __float_as_uint(b.y));
                mma_tf32(acc[2 * ntp + 1], a0, a1, a2, a3,
                         __float_as_uint(b.z), __float_as_uint(b.w));
            }
        }

        __syncthreads();   // ALL warps done reading wgt -> slabs reusable
        float* rw = red_s + wid * RED_WS;
        #pragma unroll
        for (int nt = 0; nt < 8; nt++) {
            *(float4*)(rw + nt * 132 + lane * 4) = acc[nt];
        }
    }
    __syncthreads();

    // ---------------- final: sum 8 warp-partials, scale, store --------------
    {
        const int m  = tid >> 4;          // 0..15
        const int e  = tid & 15;          // d0 = 4e
        const int nt = e >> 1;
        const int q0 = 2 * (e & 1);
        const int g4m = m & 7;
        const int up  = m >> 3;
        const int off0 = nt * 132 + (g4m * 4 + q0) * 4 + 2 * up;
        const int off1 = off0 + 4;        // q0+1

        float2 s0 = make_float2(0.f, 0.f);
        float2 s1 = make_float2(0.f, 0.f);
        #pragma unroll
        for (int w = 0; w < 8; w++) {
            const float* rp = red_s + w * RED_WS;
            const float2 p0 = *(const float2*)(rp + off0);
            const float2 p1 = *(const float2*)(rp + off1);
            s0.x += p0.x; s0.y += p0.y;
            s1.x += p1.x; s1.y += p1.y;
        }
        const float inv = inv_s[m];
        *(float4*)(out + (size_t)(m0 + m) * COUT + 4 * e) =
            make_float4(s0.x * inv, s0.y * inv, s1.x * inv, s1.y * inv);
    }
}

// ================= launch =================
extern "C" void kernel_launch(void* const* d_in, const int* in_sizes, int n_in,
                              void* d_out, int out_size) {
    const float* qpts = nullptr;
    const float* spts = nullptr;
    const float* sfeats = nullptr;
    const void*  nbr = nullptr;
    const float* wts = nullptr;
    const float* kpts = nullptr;
    for (int i = 0; i < n_in; i++) {
        switch (in_sizes[i]) {
            case MQ * 3:        qpts   = (const float*)d_in[i]; break;
            case NSUP * 3:      spts   = (const float*)d_in[i]; break;
            case NSUP * CIN:    sfeats = (const float*)d_in[i]; break;
            case MQ * HN:       nbr    = d_in[i];               break;
            case KPN*CIN*COUT:  wts    = (const float*)d_in[i]; break;
            case KPN * 3:       kpts   = (const float*)d_in[i]; break;
            default: break;
        }
    }
    float* outp = (float*)d_out;

    cudaFuncSetAttribute(kpconv_kernel,
                         cudaFuncAttributeMaxDynamicSharedMemorySize, SMEM_BYTES);

    prep_kernel<<<FLAG_BLKS + BF_BLKS + 1, 256>>>(sfeats, wts, (const unsigned*)nbr);
    kpconv_kernel<<<MQ / MB, NTHR, SMEM_BYTES>>>(
        qpts, spts, nbr, kpts, outp);
}

// round 13
// speedup vs baseline: 1.7621x; 1.0156x over previous
#include <cuda_runtime.h>
#include <cstdint>

#define MQ     50000
#define NSUP   100000
#define HN     32
#define KPN    15
#define CIN    64
#define COUT   64
#define MB     16
#define NTHR   256
#define INFPT  1.0e6f

#define NSTEPC 128                // stage-C steps over 1024 permuted contraction dim
#define WT_KS  36                 // wT k-row stride inside slab (banks 4*g4+q distinct)
#define SLAB   1028               // per-query slab: wT[0..575] then wgt[0..1023] (+pad)
#define RED_WS 1056               // per-warp partial stride (8 nt * 132)

// smem words: slabs 16*1028 + kp4 64 + inv 16 + idx 512
#define SMEM_WORDS (MB*SLAB + 64 + MB + MB*HN)
#define SMEM_BYTES (SMEM_WORDS * 4)

__device__ int g_idx_is64;
__device__ unsigned char g_flags[NSUP];
// channel-transposed tf32 sfeats: g_sfp[n][c'] = tf32(f[n][(c'&7)*8 + (c'>>3)])
// => lane (q,g4) reads b values for nt=0..7 from 8 CONSECUTIVE floats at g4*8.
__device__ float g_sfp[(size_t)NSUP * CIN];
// pair-packed fragment W: g_Bf2[(step*4+ntp)*32+lane] = {b0(d0),b1(d0),b0(d1),b1(d1)}
__device__ float4 g_Bf2[NSTEPC * 4 * 32];

__device__ __forceinline__ float to_tf32(float x) {
    uint32_t r; asm("cvt.rna.tf32.f32 %0, %1;" : "=r"(r) : "f"(x));
    return __uint_as_float(r);
}
// sqrt on the FMA pipe: bit-hack rsqrt + 2 Newton iterations. Zero MUFU.
__device__ __forceinline__ float fastsqrt(float sq) {
    float y = __uint_as_float(0x5f3759dfu - (__float_as_uint(sq) >> 1));
    const float nh = -0.5f * sq;
    y = y * fmaf(nh, y * y, 1.5f);
    y = y * fmaf(nh, y * y, 1.5f);
    return sq * y;
}
__device__ __forceinline__ void mma_tf32(float4& c, uint32_t a0, uint32_t a1,
                                         uint32_t a2, uint32_t a3,
                                         uint32_t b0, uint32_t b1) {
    asm volatile(
        "mma.sync.aligned.m16n8k8.row.col.f32.tf32.tf32.f32 "
        "{%0,%1,%2,%3}, {%4,%5,%6,%7}, {%8,%9}, {%0,%1,%2,%3};"
        : "+f"(c.x), "+f"(c.y), "+f"(c.z), "+f"(c.w)
        : "r"(a0), "r"(a1), "r"(a2), "r"(a3), "r"(b0), "r"(b1));
}

// permuted contraction index j -> W value (k<15 ? wts[k][c][d] : 0)
__device__ __forceinline__ float bf_val(const float* wts, int j, int d) {
    const int l    = (j >> 2) & 31;
    const int nt   = j >> 7;
    const int comp = j & 3;
    const int qq = l & 3;
    const int gg = l >> 2;
    const int k  = gg + ((comp >> 1) << 3);
    const int c  = (nt << 3) + (qq << 1) + (comp & 1);
    return (k < KPN) ? to_tf32(wts[(k * CIN + c) * COUT + d]) : 0.0f;
}

// ================= prep: flags + sfeats transpose-pack + B pack + detect =====
#define FLAG_BLKS ((NSUP + 7) / 8)
#define BF_BLKS   (NSTEPC * 4 * 32 / 256)    // 64
__global__ void __launch_bounds__(256) prep_kernel(const float* __restrict__ sfeats,
                                                   const float* __restrict__ wts,
                                                   const unsigned* __restrict__ nbr) {
    const int b = blockIdx.x;
    const int tid = threadIdx.x;

    if (b < FLAG_BLKS) {
        const int n = b * 8 + (tid >> 5);
        if (n >= NSUP) return;
        const int lane = tid & 31;
        const float* row = sfeats + (long long)n * CIN;
        // flags from original channel sum
        float s = row[lane] + row[lane + 32];
        #pragma unroll
        for (int o = 16; o; o >>= 1) s += __shfl_xor_sync(0xffffffffu, s, o);
        if (lane == 0) g_flags[n] = (s > 0.0f) ? 1 : 0;
        // channel-transposed pack (perm is an involution): coalesced writes
        const int cp0 = lane;          // dest c' in [0,32)
        const int cp1 = lane + 32;     // dest c' in [32,64)
        const int s0 = ((cp0 & 7) << 3) | (cp0 >> 3);
        const int s1 = ((cp1 & 7) << 3) | (cp1 >> 3);
        g_sfp[(size_t)n * CIN + cp0] = to_tf32(row[s0]);
        g_sfp[(size_t)n * CIN + cp1] = to_tf32(row[s1]);
        return;
    }
    if (b < FLAG_BLKS + BF_BLKS) {
        const int e = (b - FLAG_BLKS) * 256 + tid;   // float4 index, < 16384
        const int lane = e & 31;
        const int ntp  = (e >> 5) & 3;
        const int step = e >> 7;              // 0..127
        const int q  = lane & 3;
        const int g4 = lane >> 2;
        const int d0 = (2 * ntp) * 8 + g4;
        const int d1 = d0 + 8;
        const int j0 = step * 8 + q;
        g_Bf2[e] = make_float4(bf_val(wts, j0, d0), bf_val(wts, j0 + 4, d0),
                               bf_val(wts, j0, d1), bf_val(wts, j0 + 4, d1));
        return;
    }
    if (tid == 0) {
        int is64 = 1;
        #pragma unroll
        for (int i = 0; i < 64; i++) {
            if (nbr[2 * i + 1] != 0u) { is64 = 0; break; }
        }
        g_idx_is64 = is64;
    }
}

// ================= fused main kernel =================
extern "C" __global__ void __launch_bounds__(NTHR, 3)
kpconv_kernel(const float* __restrict__ qpts,
              const float* __restrict__ spts,
              const void*  __restrict__ nbr,
              const float* __restrict__ kpts,
              float* __restrict__ out)
{
    extern __shared__ float sm[];
    float* slab_s = sm;                         // [MB][SLAB]: wT -> wgt -> red
    float* red_s  = sm;                         // [8][RED_WS] (after wgt dead)
    float* kp4_s  = sm + MB * SLAB;             // [15][4] = {x,y,z,|kp|^2}
    float* inv_s  = kp4_s + 64;                 // MB
    int*   idx_s  = (int*)(inv_s + MB);         // [MB][HN]

    const int tid = threadIdx.x;
    const int m0  = blockIdx.x * MB;
    const bool is64 = (g_idx_is64 != 0);

    const int wid  = tid >> 5;
    const int lane = tid & 31;
    const int q    = lane & 3;
    const int g4   = lane >> 2;

    if (tid < KPN) {
        const float kx = kpts[3 * tid + 0];
        const float ky = kpts[3 * tid + 1];
        const float kz = kpts[3 * tid + 2];
        *(float4*)(kp4_s + 4 * tid) =
            make_float4(kx, ky, kz, fmaf(kx, kx, fmaf(ky, ky, kz * kz)));
    }
    __syncthreads();

    // ---------------- Stage A: w[m,h,k] -> slab wT (tf32, transposed) -------
    #pragma unroll
    for (int it = 0; it < 2; it++) {
        const int p = tid + it * NTHR;          // p < MB*HN = 512
        const int m = p >> 5;
        const int h = p & 31;
        const long long gi = (long long)(m0 + m) * HN + h;
        int idx;
        if (is64) idx = (int)((const long long*)nbr)[gi];
        else      idx = ((const int*)nbr)[gi];
        const bool valid = (idx < NSUP);

        float px, py, pz;
        if (valid) {
            const float* s3 = spts + (long long)idx * 3;
            px = s3[0]; py = s3[1]; pz = s3[2];
        } else {
            px = INFPT; py = INFPT; pz = INFPT;
        }
        const float* q3 = qpts + (long long)(m0 + m) * 3;
        const float rx = px - q3[0];
        const float ry = py - q3[1];
        const float rz = pz - q3[2];
        const float rr  = fmaf(rx, rx, fmaf(ry, ry, rz * rz));
        const float m2x = -2.0f * rx;
        const float m2y = -2.0f * ry;
        const float m2z = -2.0f * rz;

        float* wcol = slab_s + m * SLAB;        // wT region [0, 576)
        float wmax = 0.0f;
        #pragma unroll
        for (int k = 0; k < KPN; k++) {
            const float4 kp = *(const float4*)(kp4_s + 4 * k);
            const float sq0 = fmaf(m2x, kp.x,
                              fmaf(m2y, kp.y,
                              fmaf(m2z, kp.z, rr + kp.w)));
            const float sq = fmaxf(sq0, 1e-12f);
            const float w  = fmaxf(fmaf(fastsqrt(sq), -0.5f, 1.0f), 0.0f);
            wcol[k * WT_KS + h] = to_tf32(w);
            wmax = fmaxf(wmax, w);
        }
        wcol[15 * WT_KS + h] = 0.0f;            // zero pad k-row

        bool real = false;
        if (valid) real = (g_flags[idx] != 0);
        const unsigned bal = __ballot_sync(0xffffffffu, real);
        if ((tid & 31) == 0) inv_s[m] = 1.0f / (float)max(__popc(bal), 1);

        idx_s[p] = (wmax > 0.0f) ? idx : -1;
    }
    __syncthreads();

    // ---------------- Stage B (mma, warp-private): wgt = wT @ f -------------
    // warp wid owns queries 2*wid, 2*wid+1. b-operand loads are LDG.128 from
    // the channel-transposed g_sfp: lane reads 8 consecutive floats at g4*8.
    {
        #pragma unroll
        for (int half = 0; half < 2; half++) {
            const int mq = 2 * wid + half;
            const int*   irow = idx_s + mq * HN;
            const float* wtm  = slab_s + mq * SLAB;

            float4 acc[8];
            #pragma unroll
            for (int nt = 0; nt < 8; nt++) acc[nt] = make_float4(0.f, 0.f, 0.f, 0.f);

            #pragma unroll
            for (int s = 0; s < 4; s++) {
                const int h0 = s * 8;
                const uint32_t a0 = __float_as_uint(wtm[g4 * WT_KS + h0 + q]);
                const uint32_t a1 = __float_as_uint(wtm[(g4 + 8) * WT_KS + h0 + q]);
                const uint32_t a2 = __float_as_uint(wtm[g4 * WT_KS + h0 + q + 4]);
                const uint32_t a3 = __float_as_uint(wtm[(g4 + 8) * WT_KS + h0 + q + 4]);
                const int i0 = irow[h0 + q];
                const int i1 = irow[h0 + q + 4];
                const bool v0 = (i0 >= 0);
                const bool v1 = (i1 >= 0);
                const float* p0 = g_sfp + (size_t)(v0 ? i0 : 0) * CIN + g4 * 8;
                const float* p1 = g_sfp + (size_t)(v1 ? i1 : 0) * CIN + g4 * 8;
                const float4 z4 = make_float4(0.f, 0.f, 0.f, 0.f);
                // nt = 0..3
                {
                    const float4 b0 = v0 ? *(const float4*)(p0)     : z4;
                    const float4 b1 = v1 ? *(const float4*)(p1)     : z4;
                    mma_tf32(acc[0], a0, a1, a2, a3,
                             __float_as_uint(b0.x), __float_as_uint(b1.x));
                    mma_tf32(acc[1], a0, a1, a2, a3,
                             __float_as_uint(b0.y), __float_as_uint(b1.y));
                    mma_tf32(acc[2], a0, a1, a2, a3,
                             __float_as_uint(b0.z), __float_as_uint(b1.z));
                    mma_tf32(acc[3], a0, a1, a2, a3,
                             __float_as_uint(b0.w), __float_as_uint(b1.w));
                }
                // nt = 4..7
                {
                    const float4 b0 = v0 ? *(const float4*)(p0 + 4) : z4;
                    const float4 b1 = v1 ? *(const float4*)(p1 + 4) : z4;
                    mma_tf32(acc[4], a0, a1, a2, a3,
                             __float_as_uint(b0.x), __float_as_uint(b1.x));
                    mma_tf32(acc[5], a0, a1, a2, a3,
                             __float_as_uint(b0.y), __float_as_uint(b1.y));
                    mma_tf32(acc[6], a0, a1, a2, a3,
                             __float_as_uint(b0.z), __float_as_uint(b1.z));
                    mma_tf32(acc[7], a0, a1, a2, a3,
                             __float_as_uint(b0.w), __float_as_uint(b1.w));
                }
            }

            // fragment-native epilogue overwrites this query's slab (wT dead)
            float* wq = slab_s + mq * SLAB;
            #pragma unroll
            for (int nt = 0; nt < 8; nt++) {
                *(float4*)(wq + nt * 128 + lane * 4) =
                    make_float4(to_tf32(acc[nt].x), to_tf32(acc[nt].y),
                                to_tf32(acc[nt].z), to_tf32(acc[nt].w));
            }
        }
    }
    __syncthreads();

    // ---------------- Stage C (mma, warp-sliced contraction) ----------------
    // warp wid handles steps [16*wid, 16*wid+16) for ALL 8 n-tiles
    {
        float4 acc[8];
        #pragma unroll
        for (int nt = 0; nt < 8; nt++) acc[nt] = make_float4(0.f, 0.f, 0.f, 0.f);

        const float* ar0 = slab_s + g4 * SLAB;
        const float* ar1 = slab_s + (g4 + 8) * SLAB;

        #pragma unroll 4
        for (int ss = 0; ss < 16; ss++) {
            const int s  = wid * 16 + ss;
            const int k0 = s * 8;
            const uint32_t a0 = __float_as_uint(ar0[k0 + q]);
            const uint32_t a1 = __float_as_uint(ar1[k0 + q]);
            const uint32_t a2 = __float_as_uint(ar0[k0 + q + 4]);
            const uint32_t a3 = __float_as_uint(ar1[k0 + q + 4]);
            const float4* bp = g_Bf2 + (size_t)(s * 4) * 32 + lane;
            #pragma unroll
            for (int ntp = 0; ntp < 4; ntp++) {
                const float4 b = bp[ntp * 32];
                mma_tf32(acc[2 * ntp],     a0, a1, a2, a3,
                         __float_as_uint(b.x), __float_as_uint(b.y));
                mma_tf32(acc[2 * ntp + 1], a0, a1, a2, a3,
                         __float_as_uint(b.z), __float_as_uint(b.w));
            }
        }

        __syncthreads();   // ALL warps done reading wgt -> slabs reusable
        float* rw = red_s + wid * RED_WS;
        #pragma unroll
        for (int nt = 0; nt < 8; nt++) {
            *(float4*)(rw + nt * 132 + lane * 4) = acc[nt];
        }
    }
    __syncthreads();

    // ---------------- final: sum 8 warp-partials, scale, store --------------
    {
        const int m  = tid >> 4;          // 0..15
        const int e  = tid & 15;          // d0 = 4e
        const int nt = e >> 1;
        const int q0 = 2 * (e & 1);
        const int g4m = m & 7;
        const int up  = m >> 3;
        const int off0 = nt * 132 + (g4m * 4 + q0) * 4 + 2 * up;
        const int off1 = off0 + 4;        // q0+1

        float2 s0 = make_float2(0.f, 0.f);
        float2 s1 = make_float2(0.f, 0.f);
        #pragma unroll
        for (int w = 0; w < 8; w++) {
            const float* rp = red_s + w * RED_WS;
            const float2 p0 = *(const float2*)(rp + off0);
            const float2 p1 = *(const float2*)(rp + off1);
            s0.x += p0.x; s0.y += p0.y;
            s1.x += p1.x; s1.y += p1.y;
        }
        const float inv = inv_s[m];
        *(float4*)(out + (size_t)(m0 + m) * COUT + 4 * e) =
            make_float4(s0.x * inv, s0.y * inv, s1.x * inv, s1.y * inv);
    }
}

// ================= launch =================
extern "C" void kernel_launch(void* const* d_in, const int* in_sizes, int n_in,
                              void* d_out, int out_size) {
    const float* qpts = nullptr;
    const float* spts = nullptr;
    const float* sfeats = nullptr;
    const void*  nbr = nullptr;
    const float* wts = nullptr;
    const float* kpts = nullptr;
    for (int i = 0; i < n_in; i++) {
        switch (in_sizes[i]) {
            case MQ * 3:        qpts   = (const float*)d_in[i]; break;
            case NSUP * 3:      spts   = (const float*)d_in[i]; break;
            case NSUP * CIN:    sfeats = (const float*)d_in[i]; break;
            case MQ * HN:       nbr    = d_in[i];               break;
            case KPN*CIN*COUT:  wts    = (const float*)d_in[i]; break;
            case KPN * 3:       kpts   = (const float*)d_in[i]; break;
            default: break;
        }
    }
    float* outp = (float*)d_out;

    cudaFuncSetAttribute(kpconv_kernel,
                         cudaFuncAttributeMaxDynamicSharedMemorySize, SMEM_BYTES);

    prep_kernel<<<FLAG_BLKS + BF_BLKS + 1, 256>>>(sfeats, wts, (const unsigned*)nbr);
    kpconv_kernel<<<MQ / MB, NTHR, SMEM_BYTES>>>(
        qpts, spts, nbr, kpts, outp);
}

// round 14
// speedup vs baseline: 1.8101x; 1.0273x over previous
#include <cuda_runtime.h>
#include <cstdint>

#define MQ     50000
#define NSUP   100000
#define HN     32
#define KPN    15
#define CIN    64
#define COUT   64
#define MB     16
#define NTHR   256
#define INFPT  1.0e6f

#define NSTEPC 128                // stage-C steps over 1024 permuted contraction dim
#define WT_KS  36                 // wT k-row stride inside slab (banks 4*g4+q distinct)
#define SLAB   1028               // per-query slab: wT[0..575] then wgt[0..1023] (+pad)
#define RED_WS 1056               // per-warp partial stride (8 nt * 132)

// smem words: slabs 16*1028 + kp4 64 + inv 16 + idx 512
#define SMEM_WORDS (MB*SLAB + 64 + MB + MB*HN)
#define SMEM_BYTES (SMEM_WORDS * 4)

__device__ int g_idx_is64;
__device__ unsigned char g_flags[NSUP];
__device__ float4 g_sp4[NSUP];                // padded support points {x,y,z,0}
// channel-transposed tf32 sfeats: g_sfp[n][c'] = tf32(f[n][(c'&7)*8 + (c'>>3)])
__device__ float g_sfp[(size_t)NSUP * CIN];
// pair-packed fragment W: g_Bf2[(step*4+ntp)*32+lane] = {b0(d0),b1(d0),b0(d1),b1(d1)}
__device__ float4 g_Bf2[NSTEPC * 4 * 32];

__device__ __forceinline__ float to_tf32(float x) {
    uint32_t r; asm("cvt.rna.tf32.f32 %0, %1;" : "=r"(r) : "f"(x));
    return __uint_as_float(r);
}
// sqrt on the FMA pipe: bit-hack rsqrt + 2 Newton iterations. Zero MUFU.
__device__ __forceinline__ float fastsqrt(float sq) {
    float y = __uint_as_float(0x5f3759dfu - (__float_as_uint(sq) >> 1));
    const float nh = -0.5f * sq;
    y = y * fmaf(nh, y * y, 1.5f);
    y = y * fmaf(nh, y * y, 1.5f);
    return sq * y;
}
__device__ __forceinline__ void mma_tf32(float4& c, uint32_t a0, uint32_t a1,
                                         uint32_t a2, uint32_t a3,
                                         uint32_t b0, uint32_t b1) {
    asm volatile(
        "mma.sync.aligned.m16n8k8.row.col.f32.tf32.tf32.f32 "
        "{%0,%1,%2,%3}, {%4,%5,%6,%7}, {%8,%9}, {%0,%1,%2,%3};"
        : "+f"(c.x), "+f"(c.y), "+f"(c.z), "+f"(c.w)
        : "r"(a0), "r"(a1), "r"(a2), "r"(a3), "r"(b0), "r"(b1));
}

// permuted contraction index j -> W value (k<15 ? wts[k][c][d] : 0)
__device__ __forceinline__ float bf_val(const float* wts, int j, int d) {
    const int l    = (j >> 2) & 31;
    const int nt   = j >> 7;
    const int comp = j & 3;
    const int qq = l & 3;
    const int gg = l >> 2;
    const int k  = gg + ((comp >> 1) << 3);
    const int c  = (nt << 3) | (qq << 1) | (comp & 1);
    return (k < KPN) ? to_tf32(wts[(k * CIN + c) * COUT + d]) : 0.0f;
}

// ================= prep: flags + sp4 + sfeats transpose-pack + B pack ========
#define FLAG_BLKS ((NSUP + 7) / 8)
#define BF_BLKS   (NSTEPC * 4 * 32 / 256)    // 64
__global__ void __launch_bounds__(256) prep_kernel(const float* __restrict__ sfeats,
                                                   const float* __restrict__ wts,
                                                   const unsigned* __restrict__ nbr,
                                                   const float* __restrict__ spts) {
    const int b = blockIdx.x;
    const int tid = threadIdx.x;

    if (b < FLAG_BLKS) {
        const int n = b * 8 + (tid >> 5);
        if (n >= NSUP) return;
        const int lane = tid & 31;
        const float* row = sfeats + (long long)n * CIN;
        // flags from original channel sum
        float s = row[lane] + row[lane + 32];
        #pragma unroll
        for (int o = 16; o; o >>= 1) s += __shfl_xor_sync(0xffffffffu, s, o);
        if (lane == 0) {
            g_flags[n] = (s > 0.0f) ? 1 : 0;
            const float* s3 = spts + (long long)n * 3;
            g_sp4[n] = make_float4(s3[0], s3[1], s3[2], 0.0f);
        }
        // channel-transposed pack (perm is an involution): coalesced writes
        const int cp0 = lane;          // dest c' in [0,32)
        const int cp1 = lane + 32;     // dest c' in [32,64)
        const int s0 = ((cp0 & 7) << 3) | (cp0 >> 3);
        const int s1 = ((cp1 & 7) << 3) | (cp1 >> 3);
        g_sfp[(size_t)n * CIN + cp0] = to_tf32(row[s0]);
        g_sfp[(size_t)n * CIN + cp1] = to_tf32(row[s1]);
        return;
    }
    if (b < FLAG_BLKS + BF_BLKS) {
        const int e = (b - FLAG_BLKS) * 256 + tid;   // float4 index, < 16384
        const int lane = e & 31;
        const int ntp  = (e >> 5) & 3;
        const int step = e >> 7;              // 0..127
        const int q  = lane & 3;
        const int g4 = lane >> 2;
        const int d0 = (2 * ntp) * 8 + g4;
        const int d1 = d0 + 8;
        const int j0 = step * 8 + q;
        g_Bf2[e] = make_float4(bf_val(wts, j0, d0), bf_val(wts, j0 + 4, d0),
                               bf_val(wts, j0, d1), bf_val(wts, j0 + 4, d1));
        return;
    }
    if (tid == 0) {
        int is64 = 1;
        #pragma unroll
        for (int i = 0; i < 64; i++) {
            if (nbr[2 * i + 1] != 0u) { is64 = 0; break; }
        }
        g_idx_is64 = is64;
    }
}

// ================= fused main kernel =================
extern "C" __global__ void __launch_bounds__(NTHR, 3)
kpconv_kernel(const float* __restrict__ qpts,
              const void*  __restrict__ nbr,
              const float* __restrict__ kpts,
              float* __restrict__ out)
{
    extern __shared__ float sm[];
    float* slab_s = sm;                         // [MB][SLAB]: wT -> wgt -> red
    float* red_s  = sm;                         // [8][RED_WS] (after wgt dead)
    float* kp4_s  = sm + MB * SLAB;             // [15][4] = {x,y,z,|kp|^2}
    float* inv_s  = kp4_s + 64;                 // MB
    int*   idx_s  = (int*)(inv_s + MB);         // [MB][HN]

    const int tid = threadIdx.x;
    const int m0  = blockIdx.x * MB;
    const bool is64 = (g_idx_is64 != 0);

    const int wid  = tid >> 5;
    const int lane = tid & 31;
    const int q    = lane & 3;
    const int g4   = lane >> 2;

    if (tid < KPN) {
        const float kx = kpts[3 * tid + 0];
        const float ky = kpts[3 * tid + 1];
        const float kz = kpts[3 * tid + 2];
        *(float4*)(kp4_s + 4 * tid) =
            make_float4(kx, ky, kz, fmaf(kx, kx, fmaf(ky, ky, kz * kz)));
    }
    __syncthreads();

    // ---------------- Stage A: w[m,h,k] -> slab wT (tf32, transposed) -------
    #pragma unroll
    for (int it = 0; it < 2; it++) {
        const int p = tid + it * NTHR;          // p < MB*HN = 512
        const int m = p >> 5;
        const int h = p & 31;
        const long long gi = (long long)(m0 + m) * HN + h;
        int idx;
        if (is64) idx = (int)((const long long*)nbr)[gi];
        else      idx = ((const int*)nbr)[gi];
        const bool valid = (idx < NSUP);

        float4 sp = make_float4(INFPT, INFPT, INFPT, 0.0f);
        if (valid) sp = g_sp4[idx];             // single LDG.128 gather

        const float* q3 = qpts + (long long)(m0 + m) * 3;
        const float rx = sp.x - q3[0];
        const float ry = sp.y - q3[1];
        const float rz = sp.z - q3[2];
        const float rr  = fmaf(rx, rx, fmaf(ry, ry, rz * rz));
        const float m2x = -2.0f * rx;
        const float m2y = -2.0f * ry;
        const float m2z = -2.0f * rz;

        float* wcol = slab_s + m * SLAB;        // wT region [0, 576)
        float wmax = 0.0f;
        #pragma unroll
        for (int k = 0; k < KPN; k++) {
            const float4 kp = *(const float4*)(kp4_s + 4 * k);
            const float sq0 = fmaf(m2x, kp.x,
                              fmaf(m2y, kp.y,
                              fmaf(m2z, kp.z, rr + kp.w)));
            const float sq = fmaxf(sq0, 1e-12f);
            const float w  = fmaxf(fmaf(fastsqrt(sq), -0.5f, 1.0f), 0.0f);
            wcol[k * WT_KS + h] = to_tf32(w);
            wmax = fmaxf(wmax, w);
        }
        wcol[15 * WT_KS + h] = 0.0f;            // zero pad k-row

        bool real = false;
        if (valid) real = (g_flags[idx] != 0);
        const unsigned bal = __ballot_sync(0xffffffffu, real);
        if ((tid & 31) == 0) inv_s[m] = 1.0f / (float)max(__popc(bal), 1);

        idx_s[p] = (wmax > 0.0f) ? idx : -1;
    }
    __syncthreads();

    // ---------------- Stage B (mma, warp-private): wgt = wT @ f -------------
    // warp wid owns queries 2*wid, 2*wid+1. Gather loads are predicated off
    // for invalid neighbors (no dummy-row traffic).
    {
        #pragma unroll
        for (int half = 0; half < 2; half++) {
            const int mq = 2 * wid + half;
            const int*   irow = idx_s + mq * HN;
            const float* wtm  = slab_s + mq * SLAB;

            float4 acc[8];
            #pragma unroll
            for (int nt = 0; nt < 8; nt++) acc[nt] = make_float4(0.f, 0.f, 0.f, 0.f);

            #pragma unroll
            for (int s = 0; s < 4; s++) {
                const int h0 = s * 8;
                const uint32_t a0 = __float_as_uint(wtm[g4 * WT_KS + h0 + q]);
                const uint32_t a1 = __float_as_uint(wtm[(g4 + 8) * WT_KS + h0 + q]);
                const uint32_t a2 = __float_as_uint(wtm[g4 * WT_KS + h0 + q + 4]);
                const uint32_t a3 = __float_as_uint(wtm[(g4 + 8) * WT_KS + h0 + q + 4]);
                const int i0 = irow[h0 + q];
                const int i1 = irow[h0 + q + 4];
                const float4 z4 = make_float4(0.f, 0.f, 0.f, 0.f);
                float4 b00 = z4, b01 = z4, b10 = z4, b11 = z4;
                if (i0 >= 0) {
                    const float* p0 = g_sfp + (size_t)i0 * CIN + g4 * 8;
                    b00 = *(const float4*)(p0);
                    b01 = *(const float4*)(p0 + 4);
                }
                if (i1 >= 0) {
                    const float* p1 = g_sfp + (size_t)i1 * CIN + g4 * 8;
                    b10 = *(const float4*)(p1);
                    b11 = *(const float4*)(p1 + 4);
                }
                mma_tf32(acc[0], a0, a1, a2, a3,
                         __float_as_uint(b00.x), __float_as_uint(b10.x));
                mma_tf32(acc[1], a0, a1, a2, a3,
                         __float_as_uint(b00.y), __float_as_uint(b10.y));
                mma_tf32(acc[2], a0, a1, a2, a3,
                         __float_as_uint(b00.z), __float_as_uint(b10.z));
                mma_tf32(acc[3], a0, a1, a2, a3,
                         __float_as_uint(b00.w), __float_as_uint(b10.w));
                mma_tf32(acc[4], a0, a1, a2, a3,
                         __float_as_uint(b01.x), __float_as_uint(b11.x));
                mma_tf32(acc[5], a0, a1, a2, a3,
                         __float_as_uint(b01.y), __float_as_uint(b11.y));
                mma_tf32(acc[6], a0, a1, a2, a3,
                         __float_as_uint(b01.z), __float_as_uint(b11.z));
                mma_tf32(acc[7], a0, a1, a2, a3,
                         __float_as_uint(b01.w), __float_as_uint(b11.w));
            }

            // fragment-native epilogue overwrites this query's slab (wT dead)
            float* wq = slab_s + mq * SLAB;
            #pragma unroll
            for (int nt = 0; nt < 8; nt++) {
                *(float4*)(wq + nt * 128 + lane * 4) =
                    make_float4(to_tf32(acc[nt].x), to_tf32(acc[nt].y),
                                to_tf32(acc[nt].z), to_tf32(acc[nt].w));
            }
        }
    }
    __syncthreads();

    // ---------------- Stage C (mma, warp-sliced contraction) ----------------
    // warp wid handles steps [16*wid, 16*wid+16) for ALL 8 n-tiles
    {
        float4 acc[8];
        #pragma unroll
        for (int nt = 0; nt < 8; nt++) acc[nt] = make_float4(0.f, 0.f, 0.f, 0.f);

        const float* ar0 = slab_s + g4 * SLAB;
        const float* ar1 = slab_s + (g4 + 8) * SLAB;

        #pragma unroll 4
        for (int ss = 0; ss < 16; ss++) {
            const int s  = wid * 16 + ss;
            const int k0 = s * 8;
            const uint32_t a0 = __float_as_uint(ar0[k0 + q]);
            const uint32_t a1 = __float_as_uint(ar1[k0 + q]);
            const uint32_t a2 = __float_as_uint(ar0[k0 + q + 4]);
            const uint32_t a3 = __float_as_uint(ar1[k0 + q + 4]);
            const float4* bp = g_Bf2 + (size_t)(s * 4) * 32 + lane;
            #pragma unroll
            for (int ntp = 0; ntp < 4; ntp++) {
                const float4 b = bp[ntp * 32];
                mma_tf32(acc[2 * ntp],     a0, a1, a2, a3,
                         __float_as_uint(b.x), __float_as_uint(b.y));
                mma_tf32(acc[2 * ntp + 1], a0, a1, a2, a3,
                         __float_as_uint(b.z), __float_as_uint(b.w));
            }
        }

        __syncthreads();   // ALL warps done reading wgt -> slabs reusable
        float* rw = red_s + wid * RED_WS;
        #pragma unroll
        for (int nt = 0; nt < 8; nt++) {
            *(float4*)(rw + nt * 132 + lane * 4) = acc[nt];
        }
    }
    __syncthreads();

    // ---------------- final: sum 8 warp-partials, scale, store --------------
    {
        const int m  = tid >> 4;          // 0..15
        const int e  = tid & 15;          // d0 = 4e
        const int nt = e >> 1;
        const int q0 = 2 * (e & 1);
        const int g4m = m & 7;
        const int up  = m >> 3;
        const int off0 = nt * 132 + (g4m * 4 + q0) * 4 + 2 * up;
        const int off1 = off0 + 4;        // q0+1

        float2 s0 = make_float2(0.f, 0.f);
        float2 s1 = make_float2(0.f, 0.f);
        #pragma unroll
        for (int w = 0; w < 8; w++) {
            const float* rp = red_s + w * RED_WS;
            const float2 p0 = *(const float2*)(rp + off0);
            const float2 p1 = *(const float2*)(rp + off1);
            s0.x += p0.x; s0.y += p0.y;
            s1.x += p1.x; s1.y += p1.y;
        }
        const float inv = inv_s[m];
        *(float4*)(out + (size_t)(m0 + m) * COUT + 4 * e) =
            make_float4(s0.x * inv, s0.y * inv, s1.x * inv, s1.y * inv);
    }
}

// ================= launch =================
extern "C" void kernel_launch(void* const* d_in, const int* in_sizes, int n_in,
                              void* d_out, int out_size) {
    const float* qpts = nullptr;
    const float* spts = nullptr;
    const float* sfeats = nullptr;
    const void*  nbr = nullptr;
    const float* wts = nullptr;
    const float* kpts = nullptr;
    for (int i = 0; i < n_in; i++) {
        switch (in_sizes[i]) {
            case MQ * 3:        qpts   = (const float*)d_in[i]; break;
            case NSUP * 3:      spts   = (const float*)d_in[i]; break;
            case NSUP * CIN:    sfeats = (const float*)d_in[i]; break;
            case MQ * HN:       nbr    = d_in[i];               break;
            case KPN*CIN*COUT:  wts    = (const float*)d_in[i]; break;
            case KPN * 3:       kpts   = (const float*)d_in[i]; break;
            default: break;
        }
    }
    float* outp = (float*)d_out;

    cudaFuncSetAttribute(kpconv_kernel,
                         cudaFuncAttributeMaxDynamicSharedMemorySize, SMEM_BYTES);

    prep_kernel<<<FLAG_BLKS + BF_BLKS + 1, 256>>>(sfeats, wts,
                                                  (const unsigned*)nbr, spts);
    kpconv_kernel<<<MQ / MB, NTHR, SMEM_BYTES>>>(qpts, nbr, kpts, outp);
}

// round 15
// speedup vs baseline: 1.8366x; 1.0146x over previous
#include <cuda_runtime.h>
#include <cstdint>

#define MQ     50000
#define NSUP   100000
#define HN     32
#define KPN    15
#define CIN    64
#define COUT   64
#define MB     16
#define NTHR   256
#define INFPT  1.0e6f

#define NSTEPC 128                // stage-C steps over 1024 permuted contraction dim
#define WT_KS  36                 // wT k-row stride inside slab (banks 4*g4+q distinct)
#define SLAB   1028               // per-query slab: wT[0..575] then wgt[0..1023] (+pad)
#define RED_WS 1056               // per-warp partial stride (8 nt * 132)

// smem words: slabs 16*1028 + kp4 64 + inv 16 + idx 512
#define SMEM_WORDS (MB*SLAB + 64 + MB + MB*HN)
#define SMEM_BYTES (SMEM_WORDS * 4)

__device__ int g_idx_is64;
__device__ unsigned char g_flags[NSUP];
__device__ float4 g_sp4[NSUP];                // padded support points {x,y,z,0}
// gen-2 permuted tf32 sfeats: g_sfp[n][p] holds f[n][c] with
//   c = (((p>>5)*4 + (p&3)) * 8) + ((p>>2)&7)
// => lane (q,g4): nt=0..3 at p = g4*4..+3 (one 128B line per q-group),
//                 nt=4..7 at p = 32 + g4*4..+3 (the second line).
__device__ float g_sfp[(size_t)NSUP * CIN];
// pair-packed fragment W: g_Bf2[(step*4+ntp)*32+lane] = {b0(d0),b1(d0),b0(d1),b1(d1)}
__device__ float4 g_Bf2[NSTEPC * 4 * 32];

__device__ __forceinline__ float to_tf32(float x) {
    uint32_t r; asm("cvt.rna.tf32.f32 %0, %1;" : "=r"(r) : "f"(x));
    return __uint_as_float(r);
}
// sqrt on the FMA pipe: bit-hack rsqrt + 2 Newton iterations. Zero MUFU.
__device__ __forceinline__ float fastsqrt(float sq) {
    float y = __uint_as_float(0x5f3759dfu - (__float_as_uint(sq) >> 1));
    const float nh = -0.5f * sq;
    y = y * fmaf(nh, y * y, 1.5f);
    y = y * fmaf(nh, y * y, 1.5f);
    return sq * y;
}
__device__ __forceinline__ void mma_tf32(float4& c, uint32_t a0, uint32_t a1,
                                         uint32_t a2, uint32_t a3,
                                         uint32_t b0, uint32_t b1) {
    asm volatile(
        "mma.sync.aligned.m16n8k8.row.col.f32.tf32.tf32.f32 "
        "{%0,%1,%2,%3}, {%4,%5,%6,%7}, {%8,%9}, {%0,%1,%2,%3};"
        : "+f"(c.x), "+f"(c.y), "+f"(c.z), "+f"(c.w)
        : "r"(a0), "r"(a1), "r"(a2), "r"(a3), "r"(b0), "r"(b1));
}

// permuted contraction index j -> W value (k<15 ? wts[k][c][d] : 0)
__device__ __forceinline__ float bf_val(const float* wts, int j, int d) {
    const int l    = (j >> 2) & 31;
    const int nt   = j >> 7;
    const int comp = j & 3;
    const int qq = l & 3;
    const int gg = l >> 2;
    const int k  = gg + ((comp >> 1) << 3);
    const int c  = (nt << 3) | (qq << 1) | (comp & 1);
    return (k < KPN) ? to_tf32(wts[(k * CIN + c) * COUT + d]) : 0.0f;
}

// ================= prep: flags + sp4 + sfeats gen-2 pack + B pack ============
#define FLAG_BLKS ((NSUP + 7) / 8)
#define BF_BLKS   (NSTEPC * 4 * 32 / 256)    // 64
__global__ void __launch_bounds__(256) prep_kernel(const float* __restrict__ sfeats,
                                                   const float* __restrict__ wts,
                                                   const unsigned* __restrict__ nbr,
                                                   const float* __restrict__ spts) {
    const int b = blockIdx.x;
    const int tid = threadIdx.x;

    if (b < FLAG_BLKS) {
        const int n = b * 8 + (tid >> 5);
        if (n >= NSUP) return;
        const int lane = tid & 31;
        const float* row = sfeats + (long long)n * CIN;
        // flags from original channel sum
        float s = row[lane] + row[lane + 32];
        #pragma unroll
        for (int o = 16; o; o >>= 1) s += __shfl_xor_sync(0xffffffffu, s, o);
        if (lane == 0) {
            g_flags[n] = (s > 0.0f) ? 1 : 0;
            const float* s3 = spts + (long long)n * 3;
            g_sp4[n] = make_float4(s3[0], s3[1], s3[2], 0.0f);
        }
        // gen-2 permuted pack: dest p -> src c = (((p>>5)*4+(p&3))<<3) | ((p>>2)&7)
        const int p0 = lane;
        const int p1 = lane + 32;
        const int s0 = ((((p0 >> 5) << 2) | (p0 & 3)) << 3) | ((p0 >> 2) & 7);
        const int s1 = ((((p1 >> 5) << 2) | (p1 & 3)) << 3) | ((p1 >> 2) & 7);
        g_sfp[(size_t)n * CIN + p0] = to_tf32(row[s0]);
        g_sfp[(size_t)n * CIN + p1] = to_tf32(row[s1]);
        return;
    }
    if (b < FLAG_BLKS + BF_BLKS) {
        const int e = (b - FLAG_BLKS) * 256 + tid;   // float4 index, < 16384
        const int lane = e & 31;
        const int ntp  = (e >> 5) & 3;
        const int step = e >> 7;              // 0..127
        const int q  = lane & 3;
        const int g4 = lane >> 2;
        const int d0 = (2 * ntp) * 8 + g4;
        const int d1 = d0 + 8;
        const int j0 = step * 8 + q;
        g_Bf2[e] = make_float4(bf_val(wts, j0, d0), bf_val(wts, j0 + 4, d0),
                               bf_val(wts, j0, d1), bf_val(wts, j0 + 4, d1));
        return;
    }
    if (tid == 0) {
        int is64 = 1;
        #pragma unroll
        for (int i = 0; i < 64; i++) {
            if (nbr[2 * i + 1] != 0u) { is64 = 0; break; }
        }
        g_idx_is64 = is64;
    }
}

// ================= fused main kernel =================
extern "C" __global__ void __launch_bounds__(NTHR, 3)
kpconv_kernel(const float* __restrict__ qpts,
              const void*  __restrict__ nbr,
              const float* __restrict__ kpts,
              float* __restrict__ out)
{
    extern __shared__ float sm[];
    float* slab_s = sm;                         // [MB][SLAB]: wT -> wgt -> red
    float* red_s  = sm;                         // [8][RED_WS] (after wgt dead)
    float* kp4_s  = sm + MB * SLAB;             // [15][4] = {x,y,z,|kp|^2}
    float* inv_s  = kp4_s + 64;                 // MB
    int*   idx_s  = (int*)(inv_s + MB);         // [MB][HN]

    const int tid = threadIdx.x;
    const int m0  = blockIdx.x * MB;
    const bool is64 = (g_idx_is64 != 0);

    const int wid  = tid >> 5;
    const int lane = tid & 31;
    const int q    = lane & 3;
    const int g4   = lane >> 2;

    if (tid < KPN) {
        const float kx = kpts[3 * tid + 0];
        const float ky = kpts[3 * tid + 1];
        const float kz = kpts[3 * tid + 2];
        *(float4*)(kp4_s + 4 * tid) =
            make_float4(kx, ky, kz, fmaf(kx, kx, fmaf(ky, ky, kz * kz)));
    }
    __syncthreads();

    // ---------------- Stage A: w[m,h,k] -> slab wT (tf32, transposed) -------
    #pragma unroll
    for (int it = 0; it < 2; it++) {
        const int p = tid + it * NTHR;          // p < MB*HN = 512
        const int m = p >> 5;
        const int h = p & 31;
        const long long gi = (long long)(m0 + m) * HN + h;
        int idx;
        if (is64) idx = (int)((const long long*)nbr)[gi];
        else      idx = ((const int*)nbr)[gi];
        const bool valid = (idx < NSUP);

        float4 sp = make_float4(INFPT, INFPT, INFPT, 0.0f);
        if (valid) sp = g_sp4[idx];             // single LDG.128 gather

        const float* q3 = qpts + (long long)(m0 + m) * 3;
        const float rx = sp.x - q3[0];
        const float ry = sp.y - q3[1];
        const float rz = sp.z - q3[2];
        const float rr  = fmaf(rx, rx, fmaf(ry, ry, rz * rz));
        const float m2x = -2.0f * rx;
        const float m2y = -2.0f * ry;
        const float m2z = -2.0f * rz;

        float* wcol = slab_s + m * SLAB;        // wT region [0, 576)
        float wmax = 0.0f;
        #pragma unroll
        for (int k = 0; k < KPN; k++) {
            const float4 kp = *(const float4*)(kp4_s + 4 * k);
            const float sq0 = fmaf(m2x, kp.x,
                              fmaf(m2y, kp.y,
                              fmaf(m2z, kp.z, rr + kp.w)));
            const float sq = fmaxf(sq0, 1e-12f);
            const float w  = fmaxf(fmaf(fastsqrt(sq), -0.5f, 1.0f), 0.0f);
            wcol[k * WT_KS + h] = to_tf32(w);
            wmax = fmaxf(wmax, w);
        }
        wcol[15 * WT_KS + h] = 0.0f;            // zero pad k-row

        bool real = false;
        if (valid) real = (g_flags[idx] != 0);
        const unsigned bal = __ballot_sync(0xffffffffu, real);
        if ((tid & 31) == 0) inv_s[m] = 1.0f / (float)max(__popc(bal), 1);

        idx_s[p] = (wmax > 0.0f) ? idx : -1;
    }
    __syncthreads();

    // ---------------- Stage B (mma, warp-private): wgt = wT @ f -------------
    // warp wid owns queries 2*wid, 2*wid+1. Gen-2 layout: lane (q,g4) reads
    // nt0-3 at row+g4*4 (line 0) and nt4-7 at row+32+g4*4 (line 1); same-q
    // lanes tile each 128B line exactly -> 4 wf per LDG.128.
    {
        #pragma unroll
        for (int half = 0; half < 2; half++) {
            const int mq = 2 * wid + half;
            const int*   irow = idx_s + mq * HN;
            const float* wtm  = slab_s + mq * SLAB;

            float4 acc[8];
            #pragma unroll
            for (int nt = 0; nt < 8; nt++) acc[nt] = make_float4(0.f, 0.f, 0.f, 0.f);

            #pragma unroll
            for (int s = 0; s < 4; s++) {
                const int h0 = s * 8;
                const uint32_t a0 = __float_as_uint(wtm[g4 * WT_KS + h0 + q]);
                const uint32_t a1 = __float_as_uint(wtm[(g4 + 8) * WT_KS + h0 + q]);
                const uint32_t a2 = __float_as_uint(wtm[g4 * WT_KS + h0 + q + 4]);
                const uint32_t a3 = __float_as_uint(wtm[(g4 + 8) * WT_KS + h0 + q + 4]);
                const int i0 = irow[h0 + q];
                const int i1 = irow[h0 + q + 4];
                const float4 z4 = make_float4(0.f, 0.f, 0.f, 0.f);
                float4 b00 = z4, b01 = z4, b10 = z4, b11 = z4;
                if (i0 >= 0) {
                    const float* p0 = g_sfp + (size_t)i0 * CIN + g4 * 4;
                    b00 = *(const float4*)(p0);        // nt 0..3 (line 0)
                    b01 = *(const float4*)(p0 + 32);   // nt 4..7 (line 1)
                }
                if (i1 >= 0) {
                    const float* p1 = g_sfp + (size_t)i1 * CIN + g4 * 4;
                    b10 = *(const float4*)(p1);
                    b11 = *(const float4*)(p1 + 32);
                }
                mma_tf32(acc[0], a0, a1, a2, a3,
                         __float_as_uint(b00.x), __float_as_uint(b10.x));
                mma_tf32(acc[1], a0, a1, a2, a3,
                         __float_as_uint(b00.y), __float_as_uint(b10.y));
                mma_tf32(acc[2], a0, a1, a2, a3,
                         __float_as_uint(b00.z), __float_as_uint(b10.z));
                mma_tf32(acc[3], a0, a1, a2, a3,
                         __float_as_uint(b00.w), __float_as_uint(b10.w));
                mma_tf32(acc[4], a0, a1, a2, a3,
                         __float_as_uint(b01.x), __float_as_uint(b11.x));
                mma_tf32(acc[5], a0, a1, a2, a3,
                         __float_as_uint(b01.y), __float_as_uint(b11.y));
                mma_tf32(acc[6], a0, a1, a2, a3,
                         __float_as_uint(b01.z), __float_as_uint(b11.z));
                mma_tf32(acc[7], a0, a1, a2, a3,
                         __float_as_uint(b01.w), __float_as_uint(b11.w));
            }

            // fragment-native epilogue overwrites this query's slab (wT dead)
            float* wq = slab_s + mq * SLAB;
            #pragma unroll
            for (int nt = 0; nt < 8; nt++) {
                *(float4*)(wq + nt * 128 + lane * 4) =
                    make_float4(to_tf32(acc[nt].x), to_tf32(acc[nt].y),
                                to_tf32(acc[nt].z), to_tf32(acc[nt].w));
            }
        }
    }
    __syncthreads();

    // ---------------- Stage C (mma, warp-sliced contraction) ----------------
    // warp wid handles steps [16*wid, 16*wid+16) for ALL 8 n-tiles
    {
        float4 acc[8];
        #pragma unroll
        for (int nt = 0; nt < 8; nt++) acc[nt] = make_float4(0.f, 0.f, 0.f, 0.f);

        const float* ar0 = slab_s + g4 * SLAB;
        const float* ar1 = slab_s + (g4 + 8) * SLAB;

        #pragma unroll 4
        for (int ss = 0; ss < 16; ss++) {
            const int s  = wid * 16 + ss;
            const int k0 = s * 8;
            const uint32_t a0 = __float_as_uint(ar0[k0 + q]);
            const uint32_t a1 = __float_as_uint(ar1[k0 + q]);
            const uint32_t a2 = __float_as_uint(ar0[k0 + q + 4]);
            const uint32_t a3 = __float_as_uint(ar1[k0 + q + 4]);
            const float4* bp = g_Bf2 + (size_t)(s * 4) * 32 + lane;
            #pragma unroll
            for (int ntp = 0; ntp < 4; ntp++) {
                const float4 b = bp[ntp * 32];
                mma_tf32(acc[2 * ntp],     a0, a1, a2, a3,
                         __float_as_uint(b.x), __float_as_uint(b.y));
                mma_tf32(acc[2 * ntp + 1], a0, a1, a2, a3,
                         __float_as_uint(b.z), __float_as_uint(b.w));
            }
        }

        __syncthreads();   // ALL warps done reading wgt -> slabs reusable
        float* rw = red_s + wid * RED_WS;
        #pragma unroll
        for (int nt = 0; nt < 8; nt++) {
            *(float4*)(rw + nt * 132 + lane * 4) = acc[nt];
        }
    }
    __syncthreads();

    // ---------------- final: sum 8 warp-partials, scale, store --------------
    {
        const int m  = tid >> 4;          // 0..15
        const int e  = tid & 15;          // d0 = 4e
        const int nt = e >> 1;
        const int q0 = 2 * (e & 1);
        const int g4m = m & 7;
        const int up  = m >> 3;
        const int off0 = nt * 132 + (g4m * 4 + q0) * 4 + 2 * up;
        const int off1 = off0 + 4;        // q0+1

        float2 s0 = make_float2(0.f, 0.f);
        float2 s1 = make_float2(0.f, 0.f);
        #pragma unroll
        for (int w = 0; w < 8; w++) {
            const float* rp = red_s + w * RED_WS;
            const float2 p0 = *(const float2*)(rp + off0);
            const float2 p1 = *(const float2*)(rp + off1);
            s0.x += p0.x; s0.y += p0.y;
            s1.x += p1.x; s1.y += p1.y;
        }
        const float inv = inv_s[m];
        *(float4*)(out + (size_t)(m0 + m) * COUT + 4 * e) =
            make_float4(s0.x * inv, s0.y * inv, s1.x * inv, s1.y * inv);
    }
}

// ================= launch =================
extern "C" void kernel_launch(void* const* d_in, const int* in_sizes, int n_in,
                              void* d_out, int out_size) {
    const float* qpts = nullptr;
    const float* spts = nullptr;
    const float* sfeats = nullptr;
    const void*  nbr = nullptr;
    const float* wts = nullptr;
    const float* kpts = nullptr;
    for (int i = 0; i < n_in; i++) {
        switch (in_sizes[i]) {
            case MQ * 3:        qpts   = (const float*)d_in[i]; break;
            case NSUP * 3:      spts   = (const float*)d_in[i]; break;
            case NSUP * CIN:    sfeats = (const float*)d_in[i]; break;
            case MQ * HN:       nbr    = d_in[i];               break;
            case KPN*CIN*COUT:  wts    = (const float*)d_in[i]; break;
            case KPN * 3:       kpts   = (const float*)d_in[i]; break;
            default: break;
        }
    }
    float* outp = (float*)d_out;

    cudaFuncSetAttribute(kpconv_kernel,
                         cudaFuncAttributeMaxDynamicSharedMemorySize, SMEM_BYTES);

    prep_kernel<<<FLAG_BLKS + BF_BLKS + 1, 256>>>(sfeats, wts,
                                                  (const unsigned*)nbr, spts);
    kpconv_kernel<<<MQ / MB, NTHR, SMEM_BYTES>>>(qpts, nbr, kpts, outp);
}

// round 16
// speedup vs baseline: 2.2375x; 1.2183x over previous
#include <cuda_runtime.h>
#include <cuda_fp16.h>
#include <cstdint>

#define MQ     50000
#define NSUP   100000
#define HN     32
#define KPN    15
#define CIN    64
#define COUT   64
#define MB     16
#define NTHR   256
#define INFPT  1.0e6f

#define NSTEPC 128                // stage-C steps over 1024 permuted contraction dim
#define WT_KS  36                 // wT k-row stride inside slab (banks 4*g4+q distinct)
#define SLAB   1028               // per-query slab: wT[0..575] then wgt[0..1023] (+pad)
#define RED_WS 1056               // per-warp partial stride (8 nt * 132)

// smem words: slabs 16*1028 + kp4 64 + inv 16 + idx 512
#define SMEM_WORDS (MB*SLAB + 64 + MB + MB*HN)
#define SMEM_BYTES (SMEM_WORDS * 4)

__device__ int g_idx_is64;
__device__ unsigned char g_flags[NSUP];
__device__ float4 g_sp4[NSUP];                // padded support points {x,y,z,0}
// fp16 features (exact encoding of the tf32-rounded values):
//   g_sfph[n][p] = f[n][(p&7)*8 + (p>>3)]  => lane (q,g4) reads its 8 nt values
//   as ONE 16B chunk at p = g4*8 (same-q lanes tile one 128B line).
__device__ __half g_sfph[(size_t)NSUP * CIN];
// fp16 pair-packed fragment W: uint4 e=( (step*2+pp)*32 + lane ), halves
//   [4t+0]=b(j0,dA) [4t+1]=b(j0+4,dA) [4t+2]=b(j0,dB) [4t+3]=b(j0+4,dB)
//   with ntp' = 2pp+t, dA = 16*ntp'+g4, dB = dA+8, j0 = step*8+q.
__device__ uint4 g_Bf2h[NSTEPC * 2 * 32];

__device__ __forceinline__ float to_tf32(float x) {
    uint32_t r; asm("cvt.rna.tf32.f32 %0, %1;" : "=r"(r) : "f"(x));
    return __uint_as_float(r);
}
// sqrt on the FMA pipe: bit-hack rsqrt + 2 Newton iterations. Zero MUFU.
__device__ __forceinline__ float fastsqrt(float sq) {
    float y = __uint_as_float(0x5f3759dfu - (__float_as_uint(sq) >> 1));
    const float nh = -0.5f * sq;
    y = y * fmaf(nh, y * y, 1.5f);
    y = y * fmaf(nh, y * y, 1.5f);
    return sq * y;
}
__device__ __forceinline__ void mma_tf32(float4& c, uint32_t a0, uint32_t a1,
                                         uint32_t a2, uint32_t a3,
                                         uint32_t b0, uint32_t b1) {
    asm volatile(
        "mma.sync.aligned.m16n8k8.row.col.f32.tf32.tf32.f32 "
        "{%0,%1,%2,%3}, {%4,%5,%6,%7}, {%8,%9}, {%0,%1,%2,%3};"
        : "+f"(c.x), "+f"(c.y), "+f"(c.z), "+f"(c.w)
        : "r"(a0), "r"(a1), "r"(a2), "r"(a3), "r"(b0), "r"(b1));
}

// permuted contraction index j -> W value (k<15 ? wts[k][c][d] : 0)
__device__ __forceinline__ float bf_val(const float* wts, int j, int d) {
    const int l    = (j >> 2) & 31;
    const int nt   = j >> 7;
    const int comp = j & 3;
    const int qq = l & 3;
    const int gg = l >> 2;
    const int k  = gg + ((comp >> 1) << 3);
    const int c  = (nt << 3) | (qq << 1) | (comp & 1);
    return (k < KPN) ? to_tf32(wts[(k * CIN + c) * COUT + d]) : 0.0f;
}

// ================= prep: flags + sp4 + fp16 feature pack + fp16 B pack =======
#define FLAG_BLKS ((NSUP + 7) / 8)
#define BF_BLKS   (NSTEPC * 2 * 32 / 256)    // 32
__global__ void __launch_bounds__(256) prep_kernel(const float* __restrict__ sfeats,
                                                   const float* __restrict__ wts,
                                                   const unsigned* __restrict__ nbr,
                                                   const float* __restrict__ spts) {
    const int b = blockIdx.x;
    const int tid = threadIdx.x;

    if (b < FLAG_BLKS) {
        const int n = b * 8 + (tid >> 5);
        if (n >= NSUP) return;
        const int lane = tid & 31;
        const float* row = sfeats + (long long)n * CIN;
        // flags from original channel sum
        float s = row[lane] + row[lane + 32];
        #pragma unroll
        for (int o = 16; o; o >>= 1) s += __shfl_xor_sync(0xffffffffu, s, o);
        if (lane == 0) {
            g_flags[n] = (s > 0.0f) ? 1 : 0;
            const float* s3 = spts + (long long)n * 3;
            g_sp4[n] = make_float4(s3[0], s3[1], s3[2], 0.0f);
        }
        // fp16 pack: dest p -> src c = (p&7)*8 + (p>>3)
        const int p0 = lane;
        const int p1 = lane + 32;
        const int s0 = ((p0 & 7) << 3) | (p0 >> 3);
        const int s1 = ((p1 & 7) << 3) | (p1 >> 3);
        g_sfph[(size_t)n * CIN + p0] = __float2half(row[s0]);
        g_sfph[(size_t)n * CIN + p1] = __float2half(row[s1]);
        return;
    }
    if (b < FLAG_BLKS + BF_BLKS) {
        const int e = (b - FLAG_BLKS) * 256 + tid;   // uint4 index, < 8192
        const int lane = e & 31;
        const int pp   = (e >> 5) & 1;
        const int step = e >> 6;              // 0..127
        const int q  = lane & 3;
        const int g4 = lane >> 2;
        const int j0 = step * 8 + q;
        __half h[8];
        #pragma unroll
        for (int t = 0; t < 2; t++) {
            const int ntp = 2 * pp + t;
            const int dA = 16 * ntp + g4;
            const int dB = dA + 8;
            h[4 * t + 0] = __float2half(bf_val(wts, j0, dA));
            h[4 * t + 1] = __float2half(bf_val(wts, j0 + 4, dA));
            h[4 * t + 2] = __float2half(bf_val(wts, j0, dB));
            h[4 * t + 3] = __float2half(bf_val(wts, j0 + 4, dB));
        }
        g_Bf2h[e] = *(const uint4*)h;
        return;
    }
    if (tid == 0) {
        int is64 = 1;
        #pragma unroll
        for (int i = 0; i < 64; i++) {
            if (nbr[2 * i + 1] != 0u) { is64 = 0; break; }
        }
        g_idx_is64 = is64;
    }
}

// ================= fused main kernel =================
extern "C" __global__ void __launch_bounds__(NTHR, 3)
kpconv_kernel(const float* __restrict__ qpts,
              const void*  __restrict__ nbr,
              const float* __restrict__ kpts,
              float* __restrict__ out)
{
    extern __shared__ float sm[];
    float* slab_s = sm;                         // [MB][SLAB]: wT -> wgt -> red
    float* red_s  = sm;                         // [8][RED_WS] (after wgt dead)
    float* kp4_s  = sm + MB * SLAB;             // [15][4] = {x,y,z,|kp|^2}
    float* inv_s  = kp4_s + 64;                 // MB
    int*   idx_s  = (int*)(inv_s + MB);         // [MB][HN]

    const int tid = threadIdx.x;
    const int m0  = blockIdx.x * MB;
    const bool is64 = (g_idx_is64 != 0);

    const int wid  = tid >> 5;
    const int lane = tid & 31;
    const int q    = lane & 3;
    const int g4   = lane >> 2;

    if (tid < KPN) {
        const float kx = kpts[3 * tid + 0];
        const float ky = kpts[3 * tid + 1];
        const float kz = kpts[3 * tid + 2];
        *(float4*)(kp4_s + 4 * tid) =
            make_float4(kx, ky, kz, fmaf(kx, kx, fmaf(ky, ky, kz * kz)));
    }
    __syncthreads();

    // ---------------- Stage A: w[m,h,k] -> slab wT (tf32, transposed) -------
    #pragma unroll
    for (int it = 0; it < 2; it++) {
        const int p = tid + it * NTHR;          // p < MB*HN = 512
        const int m = p >> 5;
        const int h = p & 31;
        const long long gi = (long long)(m0 + m) * HN + h;
        int idx;
        if (is64) idx = (int)((const long long*)nbr)[gi];
        else      idx = ((const int*)nbr)[gi];
        const bool valid = (idx < NSUP);

        float4 sp = make_float4(INFPT, INFPT, INFPT, 0.0f);
        if (valid) sp = g_sp4[idx];             // single LDG.128 gather

        const float* q3 = qpts + (long long)(m0 + m) * 3;
        const float rx = sp.x - q3[0];
        const float ry = sp.y - q3[1];
        const float rz = sp.z - q3[2];
        const float rr  = fmaf(rx, rx, fmaf(ry, ry, rz * rz));
        const float m2x = -2.0f * rx;
        const float m2y = -2.0f * ry;
        const float m2z = -2.0f * rz;

        float* wcol = slab_s + m * SLAB;        // wT region [0, 576)
        float wmax = 0.0f;
        #pragma unroll
        for (int k = 0; k < KPN; k++) {
            const float4 kp = *(const float4*)(kp4_s + 4 * k);
            const float sq0 = fmaf(m2x, kp.x,
                              fmaf(m2y, kp.y,
                              fmaf(m2z, kp.z, rr + kp.w)));
            const float sq = fmaxf(sq0, 1e-12f);
            const float w  = fmaxf(fmaf(fastsqrt(sq), -0.5f, 1.0f), 0.0f);
            wcol[k * WT_KS + h] = to_tf32(w);
            wmax = fmaxf(wmax, w);
        }
        wcol[15 * WT_KS + h] = 0.0f;            // zero pad k-row

        bool real = false;
        if (valid) real = (g_flags[idx] != 0);
        const unsigned bal = __ballot_sync(0xffffffffu, real);
        if ((tid & 31) == 0) inv_s[m] = 1.0f / (float)max(__popc(bal), 1);

        idx_s[p] = (wmax > 0.0f) ? idx : -1;
    }
    __syncthreads();

    // ---------------- Stage B (mma, warp-private): wgt = wT @ f -------------
    // warp wid owns queries 2*wid, 2*wid+1. Each valid row's 8 nt values load
    // as ONE LDG.128 of fp16 (same-q lanes tile a 128B line exactly).
    {
        #pragma unroll
        for (int half = 0; half < 2; half++) {
            const int mq = 2 * wid + half;
            const int*   irow = idx_s + mq * HN;
            const float* wtm  = slab_s + mq * SLAB;

            float4 acc[8];
            #pragma unroll
            for (int nt = 0; nt < 8; nt++) acc[nt] = make_float4(0.f, 0.f, 0.f, 0.f);

            #pragma unroll
            for (int s = 0; s < 4; s++) {
                const int h0 = s * 8;
                const uint32_t a0 = __float_as_uint(wtm[g4 * WT_KS + h0 + q]);
                const uint32_t a1 = __float_as_uint(wtm[(g4 + 8) * WT_KS + h0 + q]);
                const uint32_t a2 = __float_as_uint(wtm[g4 * WT_KS + h0 + q + 4]);
                const uint32_t a3 = __float_as_uint(wtm[(g4 + 8) * WT_KS + h0 + q + 4]);
                const int i0 = irow[h0 + q];
                const int i1 = irow[h0 + q + 4];
                uint4 u0 = make_uint4(0u, 0u, 0u, 0u);
                uint4 u1 = make_uint4(0u, 0u, 0u, 0u);
                if (i0 >= 0)
                    u0 = *(const uint4*)(g_sfph + (size_t)i0 * CIN + g4 * 8);
                if (i1 >= 0)
                    u1 = *(const uint4*)(g_sfph + (size_t)i1 * CIN + g4 * 8);
                const __half2* h0p = (const __half2*)&u0;
                const __half2* h1p = (const __half2*)&u1;
                #pragma unroll
                for (int j = 0; j < 4; j++) {      // nt pair (2j, 2j+1)
                    const float2 f0 = __half22float2(h0p[j]);
                    const float2 f1 = __half22float2(h1p[j]);
                    mma_tf32(acc[2 * j],     a0, a1, a2, a3,
                             __float_as_uint(f0.x), __float_as_uint(f1.x));
                    mma_tf32(acc[2 * j + 1], a0, a1, a2, a3,
                             __float_as_uint(f0.y), __float_as_uint(f1.y));
                }
            }

            // fragment-native epilogue overwrites this query's slab (wT dead)
            float* wq = slab_s + mq * SLAB;
            #pragma unroll
            for (int nt = 0; nt < 8; nt++) {
                *(float4*)(wq + nt * 128 + lane * 4) =
                    make_float4(to_tf32(acc[nt].x), to_tf32(acc[nt].y),
                                to_tf32(acc[nt].z), to_tf32(acc[nt].w));
            }
        }
    }
    __syncthreads();

    // ---------------- Stage C (mma, warp-sliced contraction) ----------------
    // warp wid handles steps [16*wid, 16*wid+16) for ALL 8 n-tiles.
    // B stream is fp16: 2 LDG.128 per step instead of 4.
    {
        float4 acc[8];
        #pragma unroll
        for (int nt = 0; nt < 8; nt++) acc[nt] = make_float4(0.f, 0.f, 0.f, 0.f);

        const float* ar0 = slab_s + g4 * SLAB;
        const float* ar1 = slab_s + (g4 + 8) * SLAB;

        #pragma unroll 4
        for (int ss = 0; ss < 16; ss++) {
            const int s  = wid * 16 + ss;
            const int k0 = s * 8;
            const uint32_t a0 = __float_as_uint(ar0[k0 + q]);
            const uint32_t a1 = __float_as_uint(ar1[k0 + q]);
            const uint32_t a2 = __float_as_uint(ar0[k0 + q + 4]);
            const uint32_t a3 = __float_as_uint(ar1[k0 + q + 4]);
            const uint4* bp = g_Bf2h + (size_t)(s * 2) * 32 + lane;
            #pragma unroll
            for (int pp = 0; pp < 2; pp++) {
                const uint4 u = bp[pp * 32];
                const __half2* hp = (const __half2*)&u;
                #pragma unroll
                for (int t = 0; t < 2; t++) {       // ntp' = 2pp + t
                    const int ntp = 2 * pp + t;
                    const float2 pA = __half22float2(hp[2 * t]);     // (b0 dA, b1 dA)
                    const float2 pB = __half22float2(hp[2 * t + 1]); // (b0 dB, b1 dB)
                    mma_tf32(acc[2 * ntp],     a0, a1, a2, a3,
                             __float_as_uint(pA.x), __float_as_uint(pA.y));
                    mma_tf32(acc[2 * ntp + 1], a0, a1, a2, a3,
                             __float_as_uint(pB.x), __float_as_uint(pB.y));
                }
            }
        }

        __syncthreads();   // ALL warps done reading wgt -> slabs reusable
        float* rw = red_s + wid * RED_WS;
        #pragma unroll
        for (int nt = 0; nt < 8; nt++) {
            *(float4*)(rw + nt * 132 + lane * 4) = acc[nt];
        }
    }
    __syncthreads();

    // ---------------- final: sum 8 warp-partials, scale, store --------------
    {
        const int m  = tid >> 4;          // 0..15
        const int e  = tid & 15;          // d0 = 4e
        const int nt = e >> 1;
        const int q0 = 2 * (e & 1);
        const int g4m = m & 7;
        const int up  = m >> 3;
        const int off0 = nt * 132 + (g4m * 4 + q0) * 4 + 2 * up;
        const int off1 = off0 + 4;        // q0+1

        float2 s0 = make_float2(0.f, 0.f);
        float2 s1 = make_float2(0.f, 0.f);
        #pragma unroll
        for (int w = 0; w < 8; w++) {
            const float* rp = red_s + w * RED_WS;
            const float2 p0 = *(const float2*)(rp + off0);
            const float2 p1 = *(const float2*)(rp + off1);
            s0.x += p0.x; s0.y += p0.y;
            s1.x += p1.x; s1.y += p1.y;
        }
        const float inv = inv_s[m];
        *(float4*)(out + (size_t)(m0 + m) * COUT + 4 * e) =
            make_float4(s0.x * inv, s0.y * inv, s1.x * inv, s1.y * inv);
    }
}

// ================= launch =================
extern "C" void kernel_launch(void* const* d_in, const int* in_sizes, int n_in,
                              void* d_out, int out_size) {
    const float* qpts = nullptr;
    const float* spts = nullptr;
    const float* sfeats = nullptr;
    const void*  nbr = nullptr;
    const float* wts = nullptr;
    const float* kpts = nullptr;
    for (int i = 0; i < n_in; i++) {
        switch (in_sizes[i]) {
            case MQ * 3:        qpts   = (const float*)d_in[i]; break;
            case NSUP * 3:      spts   = (const float*)d_in[i]; break;
            case NSUP * CIN:    sfeats = (const float*)d_in[i]; break;
            case MQ * HN:       nbr    = d_in[i];               break;
            case KPN*CIN*COUT:  wts    = (const float*)d_in[i]; break;
            case KPN * 3:       kpts   = (const float*)d_in[i]; break;
            default: break;
        }
    }
    float* outp = (float*)d_out;

    cudaFuncSetAttribute(kpconv_kernel,
                         cudaFuncAttributeMaxDynamicSharedMemorySize, SMEM_BYTES);

    prep_kernel<<<FLAG_BLKS + BF_BLKS + 1, 256>>>(sfeats, wts,
                                                  (const unsigned*)nbr, spts);
    kpconv_kernel<<<MQ / MB, NTHR, SMEM_BYTES>>>(qpts, nbr, kpts, outp);
}

// round 17
// speedup vs baseline: 2.7812x; 1.2430x over previous
#include <cuda_runtime.h>
#include <cuda_fp16.h>
#include <cstdint>

#define MQ     50000
#define NSUP   100000
#define HN     32
#define KPN    15
#define CIN    64
#define COUT   64
#define MB     16
#define NTHR   256
#define INFPT  1.0e6f

#define NSTEP16 64                // stage-C k16 steps over 1024 permuted contraction
#define WT_ST  40                 // wT k-row stride in halves (banks 20*g4+q distinct)
#define SLAB_H 1064               // per-query slab in halves (532%32==20 -> conflict-free)
#define RED_WS 1056               // per-warp fp32 partial stride (8 nt * 132)

// smem bytes: slabs 16*1064*2 + kp4 64*4 + inv 16*4 + idx 512*4
#define SMEM_BYTES (MB*SLAB_H*2 + 64*4 + MB*4 + MB*HN*4)

__device__ int g_idx_is64;
__device__ unsigned char g_flags[NSUP];
__device__ float4 g_sp4[NSUP];                // padded support points {x,y,z,0}
// fp16 features: g_sfph[n][p] = f[n][(p&7)*8 + (p>>3)]; lane (q,g4) reads its
// 8 nt values as ONE 16B chunk at p = g4*8.
__device__ __half g_sfph[(size_t)NSUP * CIN];
// fp16 b-fragment pack for stage C (m16n8k16): e = (s*4+pp)*32+lane, halves:
//  [0]=B[16s+2q][dA] [1]=B[16s+2q+1][dA] [2]=B[16s+2q+8][dA] [3]=B[16s+2q+9][dA]
//  [4..7] same with dB;  dA = 8*(2pp)+g4, dB = 8*(2pp+1)+g4.
__device__ uint4 g_Bch[NSTEP16 * 4 * 32];

// sqrt on the FMA pipe: bit-hack rsqrt + 2 Newton iterations. Zero MUFU.
__device__ __forceinline__ float fastsqrt(float sq) {
    float y = __uint_as_float(0x5f3759dfu - (__float_as_uint(sq) >> 1));
    const float nh = -0.5f * sq;
    y = y * fmaf(nh, y * y, 1.5f);
    y = y * fmaf(nh, y * y, 1.5f);
    return sq * y;
}
__device__ __forceinline__ void mma_f16(float4& c, uint32_t a0, uint32_t a1,
                                        uint32_t a2, uint32_t a3,
                                        uint32_t b0, uint32_t b1) {
    asm volatile(
        "mma.sync.aligned.m16n8k16.row.col.f32.f16.f16.f32 "
        "{%0,%1,%2,%3}, {%4,%5,%6,%7}, {%8,%9}, {%0,%1,%2,%3};"
        : "+f"(c.x), "+f"(c.y), "+f"(c.z), "+f"(c.w)
        : "r"(a0), "r"(a1), "r"(a2), "r"(a3), "r"(b0), "r"(b1));
}
__device__ __forceinline__ uint32_t prmt(uint32_t a, uint32_t b, uint32_t sel) {
    uint32_t r; asm("prmt.b32 %0, %1, %2, %3;" : "=r"(r) : "r"(a), "r"(b), "r"(sel));
    return r;
}
__device__ __forceinline__ uint32_t h2u(__half2 h) {
    uint32_t r; asm("mov.b32 %0, %1;" : "=r"(r) : "r"(*(uint32_t*)&h));
    return r;
}

// permuted contraction index j -> W value (k<15 ? wts[k][c][d] : 0), fp16
__device__ __forceinline__ __half bh_val(const float* wts, int j, int d) {
    const int l    = (j >> 2) & 31;
    const int nt   = j >> 7;
    const int comp = j & 3;
    const int qq = l & 3;
    const int gg = l >> 2;
    const int k  = gg + ((comp >> 1) << 3);
    const int c  = (nt << 3) | (qq << 1) | (comp & 1);
    return __float2half((k < KPN) ? wts[(k * CIN + c) * COUT + d] : 0.0f);
}

// ================= prep: flags + sp4 + fp16 feature pack + b-frag pack =======
#define FLAG_BLKS ((NSUP + 7) / 8)
#define BF_BLKS   (NSTEP16 * 4 * 32 / 256)   // 32
__global__ void __launch_bounds__(256) prep_kernel(const float* __restrict__ sfeats,
                                                   const float* __restrict__ wts,
                                                   const unsigned* __restrict__ nbr,
                                                   const float* __restrict__ spts) {
    const int b = blockIdx.x;
    const int tid = threadIdx.x;

    if (b < FLAG_BLKS) {
        const int n = b * 8 + (tid >> 5);
        if (n >= NSUP) return;
        const int lane = tid & 31;
        const float* row = sfeats + (long long)n * CIN;
        float s = row[lane] + row[lane + 32];
        #pragma unroll
        for (int o = 16; o; o >>= 1) s += __shfl_xor_sync(0xffffffffu, s, o);
        if (lane == 0) {
            g_flags[n] = (s > 0.0f) ? 1 : 0;
            const float* s3 = spts + (long long)n * 3;
            g_sp4[n] = make_float4(s3[0], s3[1], s3[2], 0.0f);
        }
        const int p0 = lane;
        const int p1 = lane + 32;
        const int s0 = ((p0 & 7) << 3) | (p0 >> 3);
        const int s1 = ((p1 & 7) << 3) | (p1 >> 3);
        g_sfph[(size_t)n * CIN + p0] = __float2half(row[s0]);
        g_sfph[(size_t)n * CIN + p1] = __float2half(row[s1]);
        return;
    }
    if (b < FLAG_BLKS + BF_BLKS) {
        const int e = (b - FLAG_BLKS) * 256 + tid;   // uint4 index, < 8192
        const int lane = e & 31;
        const int pp   = (e >> 5) & 3;
        const int s16  = e >> 7;              // 0..63
        const int q  = lane & 3;
        const int g4 = lane >> 2;
        const int j0 = s16 * 16 + 2 * q;
        __half h[8];
        #pragma unroll
        for (int t = 0; t < 2; t++) {
            const int d = 8 * (2 * pp + t) + g4;
            h[4 * t + 0] = bh_val(wts, j0,     d);
            h[4 * t + 1] = bh_val(wts, j0 + 1, d);
            h[4 * t + 2] = bh_val(wts, j0 + 8, d);
            h[4 * t + 3] = bh_val(wts, j0 + 9, d);
        }
        g_Bch[e] = *(const uint4*)h;
        return;
    }
    if (tid == 0) {
        int is64 = 1;
        #pragma unroll
        for (int i = 0; i < 64; i++) {
            if (nbr[2 * i + 1] != 0u) { is64 = 0; break; }
        }
        g_idx_is64 = is64;
    }
}

// ================= fused main kernel =================
extern "C" __global__ void __launch_bounds__(NTHR, 3)
kpconv_kernel(const float* __restrict__ qpts,
              const void*  __restrict__ nbr,
              const float* __restrict__ kpts,
              float* __restrict__ out)
{
    extern __shared__ float sm[];
    __half* slab_h = (__half*)sm;               // [MB][SLAB_H]: wT(fp16) -> wgt(fp16)
    float*  red_s  = sm;                        // [8][RED_WS] fp32 (after wgt dead)
    float*  kp4_s  = sm + (MB * SLAB_H) / 2;    // [15][4] = {x,y,z,|kp|^2}
    float*  inv_s  = kp4_s + 64;                // MB
    int*    idx_s  = (int*)(inv_s + MB);        // [MB][HN]

    const int tid = threadIdx.x;
    const int m0  = blockIdx.x * MB;
    const bool is64 = (g_idx_is64 != 0);

    const int wid  = tid >> 5;
    const int lane = tid & 31;
    const int q    = lane & 3;
    const int g4   = lane >> 2;

    if (tid < KPN) {
        const float kx = kpts[3 * tid + 0];
        const float ky = kpts[3 * tid + 1];
        const float kz = kpts[3 * tid + 2];
        *(float4*)(kp4_s + 4 * tid) =
            make_float4(kx, ky, kz, fmaf(kx, kx, fmaf(ky, ky, kz * kz)));
    }
    __syncthreads();

    // ---------------- Stage A: w[m,h,k] -> slab wT (fp16, transposed) -------
    #pragma unroll
    for (int it = 0; it < 2; it++) {
        const int p = tid + it * NTHR;          // p < MB*HN = 512
        const int m = p >> 5;
        const int h = p & 31;
        const long long gi = (long long)(m0 + m) * HN + h;
        int idx;
        if (is64) idx = (int)((const long long*)nbr)[gi];
        else      idx = ((const int*)nbr)[gi];
        const bool valid = (idx < NSUP);

        float4 sp = make_float4(INFPT, INFPT, INFPT, 0.0f);
        if (valid) sp = g_sp4[idx];             // single LDG.128 gather

        const float* q3 = qpts + (long long)(m0 + m) * 3;
        const float rx = sp.x - q3[0];
        const float ry = sp.y - q3[1];
        const float rz = sp.z - q3[2];
        const float rr  = fmaf(rx, rx, fmaf(ry, ry, rz * rz));
        const float m2x = -2.0f * rx;
        const float m2y = -2.0f * ry;
        const float m2z = -2.0f * rz;

        __half* wcol = slab_h + m * SLAB_H;     // wT region [0, 640) halves
        float wmax = 0.0f;
        #pragma unroll
        for (int k = 0; k < KPN; k++) {
            const float4 kp = *(const float4*)(kp4_s + 4 * k);
            const float sq0 = fmaf(m2x, kp.x,
                              fmaf(m2y, kp.y,
                              fmaf(m2z, kp.z, rr + kp.w)));
            const float sq = fmaxf(sq0, 1e-12f);
            const float w  = fmaxf(fmaf(fastsqrt(sq), -0.5f, 1.0f), 0.0f);
            wcol[k * WT_ST + h] = __float2half(w);
            wmax = fmaxf(wmax, w);
        }
        wcol[15 * WT_ST + h] = __float2half(0.0f);  // zero pad k-row

        bool real = false;
        if (valid) real = (g_flags[idx] != 0);
        const unsigned bal = __ballot_sync(0xffffffffu, real);
        if ((tid & 31) == 0) inv_s[m] = 1.0f / (float)max(__popc(bal), 1);

        idx_s[p] = (wmax > 0.0f) ? idx : -1;
    }
    __syncthreads();

    // ---------------- Stage B (fp16 mma k16): wgt = wT(16x32) @ f(32x64) ----
    // warp wid owns queries 2*wid, 2*wid+1.
    {
        #pragma unroll
        for (int half = 0; half < 2; half++) {
            const int mq = 2 * wid + half;
            const int*    irow = idx_s + mq * HN;
            const __half* wtm  = slab_h + mq * SLAB_H;

            float4 acc[8];
            #pragma unroll
            for (int nt = 0; nt < 8; nt++) acc[nt] = make_float4(0.f, 0.f, 0.f, 0.f);

            #pragma unroll
            for (int s = 0; s < 2; s++) {
                const int h0 = 16 * s;
                // a-fragments: 4 LDS.32 (conflict-free: banks 20*g4+q+8s)
                const uint32_t ra0 = *(const uint32_t*)(wtm + g4 * WT_ST + h0 + 2 * q);
                const uint32_t ra1 = *(const uint32_t*)(wtm + (g4 + 8) * WT_ST + h0 + 2 * q);
                const uint32_t ra2 = *(const uint32_t*)(wtm + g4 * WT_ST + h0 + 2 * q + 8);
                const uint32_t ra3 = *(const uint32_t*)(wtm + (g4 + 8) * WT_ST + h0 + 2 * q + 8);
                // gather 4 neighbor rows (h = h0 + 2q, 2q+1, 2q+8, 2q+9)
                const int i0 = irow[h0 + 2 * q];
                const int i1 = irow[h0 + 2 * q + 1];
                const int i2 = irow[h0 + 2 * q + 8];
                const int i3 = irow[h0 + 2 * q + 9];
                uint4 u0 = make_uint4(0, 0, 0, 0), u1 = make_uint4(0, 0, 0, 0);
                uint4 u2 = make_uint4(0, 0, 0, 0), u3 = make_uint4(0, 0, 0, 0);
                if (i0 >= 0) u0 = *(const uint4*)(g_sfph + (size_t)i0 * CIN + g4 * 8);
                if (i1 >= 0) u1 = *(const uint4*)(g_sfph + (size_t)i1 * CIN + g4 * 8);
                if (i2 >= 0) u2 = *(const uint4*)(g_sfph + (size_t)i2 * CIN + g4 * 8);
                if (i3 >= 0) u3 = *(const uint4*)(g_sfph + (size_t)i3 * CIN + g4 * 8);
                const uint32_t* w0 = (const uint32_t*)&u0;
                const uint32_t* w1 = (const uint32_t*)&u1;
                const uint32_t* w2 = (const uint32_t*)&u2;
                const uint32_t* w3 = (const uint32_t*)&u3;
                #pragma unroll
                for (int j = 0; j < 4; j++) {        // component j -> nt 2j, 2j+1
                    const uint32_t bl0 = prmt(w0[j], w1[j], 0x5410u);  // nt=2j, rows 2q/2q+1
                    const uint32_t bl1 = prmt(w2[j], w3[j], 0x5410u);  // nt=2j, rows 2q+8/+9
                    mma_f16(acc[2 * j], ra0, ra1, ra2, ra3, bl0, bl1);
                    const uint32_t bh0 = prmt(w0[j], w1[j], 0x7632u);  // nt=2j+1
                    const uint32_t bh1 = prmt(w2[j], w3[j], 0x7632u);
                    mma_f16(acc[2 * j + 1], ra0, ra1, ra2, ra3, bh0, bh1);
                }
            }

            // fp16 fragment-native epilogue (same j positions as before, halves)
            __half* wq = slab_h + mq * SLAB_H;
            #pragma unroll
            for (int nt = 0; nt < 8; nt++) {
                const __half2 hxy = __floats2half2_rn(acc[nt].x, acc[nt].y);
                const __half2 hzw = __floats2half2_rn(acc[nt].z, acc[nt].w);
                uint2 pk;
                pk.x = h2u(hxy);
                pk.y = h2u(hzw);
                *(uint2*)(wq + nt * 128 + lane * 4) = pk;   // STS.64
            }
        }
    }
    __syncthreads();

    // ---------------- Stage C (fp16 mma k16, warp-sliced) -------------------
    // warp wid handles k16 steps [8*wid, 8*wid+8) for ALL 8 n-tiles
    {
        float4 acc[8];
        #pragma unroll
        for (int nt = 0; nt < 8; nt++) acc[nt] = make_float4(0.f, 0.f, 0.f, 0.f);

        const __half* ar0 = slab_h + g4 * SLAB_H;
        const __half* ar1 = slab_h + (g4 + 8) * SLAB_H;

        #pragma unroll 2
        for (int ss = 0; ss < 8; ss++) {
            const int s  = wid * 8 + ss;
            const int j0 = s * 16 + 2 * q;
            const uint32_t ra0 = *(const uint32_t*)(ar0 + j0);
            const uint32_t ra1 = *(const uint32_t*)(ar1 + j0);
            const uint32_t ra2 = *(const uint32_t*)(ar0 + j0 + 8);
            const uint32_t ra3 = *(const uint32_t*)(ar1 + j0 + 8);
            const uint4* bp = g_Bch + (size_t)(s * 4) * 32 + lane;
            #pragma unroll
            for (int pp = 0; pp < 4; pp++) {
                const uint4 u = bp[pp * 32];
                mma_f16(acc[2 * pp],     ra0, ra1, ra2, ra3, u.x, u.y);
                mma_f16(acc[2 * pp + 1], ra0, ra1, ra2, ra3, u.z, u.w);
            }
        }

        __syncthreads();   // ALL warps done reading wgt -> slabs reusable
        float* rw = red_s + wid * RED_WS;
        #pragma unroll
        for (int nt = 0; nt < 8; nt++) {
            *(float4*)(rw + nt * 132 + lane * 4) = acc[nt];
        }
    }
    __syncthreads();

    // ---------------- final: sum 8 warp-partials, scale, store --------------
    {
        const int m  = tid >> 4;          // 0..15
        const int e  = tid & 15;          // d0 = 4e
        const int nt = e >> 1;
        const int q0 = 2 * (e & 1);
        const int g4m = m & 7;
        const int up  = m >> 3;
        const int off0 = nt * 132 + (g4m * 4 + q0) * 4 + 2 * up;
        const int off1 = off0 + 4;        // q0+1

        float2 s0 = make_float2(0.f, 0.f);
        float2 s1 = make_float2(0.f, 0.f);
        #pragma unroll
        for (int w = 0; w < 8; w++) {
            const float* rp = red_s + w * RED_WS;
            const float2 p0 = *(const float2*)(rp + off0);
            const float2 p1 = *(const float2*)(rp + off1);
            s0.x += p0.x; s0.y += p0.y;
            s1.x += p1.x; s1.y += p1.y;
        }
        const float inv = inv_s[m];
        *(float4*)(out + (size_t)(m0 + m) * COUT + 4 * e) =
            make_float4(s0.x * inv, s0.y * inv, s1.x * inv, s1.y * inv);
    }
}

// ================= launch =================
extern "C" void kernel_launch(void* const* d_in, const int* in_sizes, int n_in,
                              void* d_out, int out_size) {
    const float* qpts = nullptr;
    const float* spts = nullptr;
    const float* sfeats = nullptr;
    const void*  nbr = nullptr;
    const float* wts = nullptr;
    const float* kpts = nullptr;
    for (int i = 0; i < n_in; i++) {
        switch (in_sizes[i]) {
            case MQ * 3:        qpts   = (const float*)d_in[i]; break;
            case NSUP * 3:      spts   = (const float*)d_in[i]; break;
            case NSUP * CIN:    sfeats = (const float*)d_in[i]; break;
            case MQ * HN:       nbr    = d_in[i];               break;
            case KPN*CIN*COUT:  wts    = (const float*)d_in[i]; break;
            case KPN * 3:       kpts   = (const float*)d_in[i]; break;
            default: break;
        }
    }
    float* outp = (float*)d_out;

    cudaFuncSetAttribute(kpconv_kernel,
                         cudaFuncAttributeMaxDynamicSharedMemorySize, SMEM_BYTES);

    prep_kernel<<<FLAG_BLKS + BF_BLKS + 1, 256>>>(sfeats, wts,
                                                  (const unsigned*)nbr, spts);
    kpconv_kernel<<<MQ / MB, NTHR, SMEM_BYTES>>>(qpts, nbr, kpts, outp);
}